// round 13
// baseline (speedup 1.0000x reference)
#include <cuda_runtime.h>
#include <cuda_bf16.h>
#include <cstdint>
#include <math.h>

#define B      512
#define S      200
#define H      1024
#define V      100
#define EMB    512
#define INSZ   1024
#define H3     3072
#define START_TOK 1
#define NTH    512

// smem (bytes): rows padded to 40 bf16 (80B) for conflict-free LDSM
#define OFF_AXH 0u
#define OFF_AXL 10240u
#define OFF_AHH 20480u
#define OFF_AHL 30720u
#define OFF_WH  40960u
#define OFF_WL  56320u
#define BUFSTRIDE 71680u
#define SMEM_TOTAL 143360

// ---------------- fp32 scratch ----------------
__device__ float g_h0[B * H];
__device__ float g_h1[B * H];
__device__ float g_h2[B * H];
__device__ float g_gi0c[B * H3];
__device__ float g_tokt[V * H3];
__device__ float g_logc[B * V];
__device__ float g_bc0[3072];
__device__ float g_bc1[6144];
__device__ float g_bc2[6144];
__device__ unsigned g_bar_count;
__device__ unsigned g_bar_phase;
__device__ unsigned g_cntA[8];
__device__ unsigned g_cntC[4];
__device__ unsigned g_cntE[4];
__device__ unsigned g_cntL[4];

// ---------------- bf16 splits ----------------
__device__ __align__(16) __nv_bfloat16 g_wc0h[3072 * H], g_wc0l[3072 * H];
__device__ __align__(16) __nv_bfloat16 g_wc1h[6144 * H], g_wc1l[6144 * H];
__device__ __align__(16) __nv_bfloat16 g_wc2h[6144 * H], g_wc2l[6144 * H];
__device__ __align__(16) __nv_bfloat16 g_owh[128 * H],  g_owl[128 * H];
__device__ __align__(16) __nv_bfloat16 g_ow2h[128 * H], g_ow2l[128 * H];
__device__ __align__(16) __nv_bfloat16 g_i2hh[H * INSZ], g_i2hl[H * INSZ];
__device__ __align__(16) __nv_bfloat16 g_w0ah[H3 * EMB], g_w0al[H3 * EMB];
__device__ __align__(16) __nv_bfloat16 g_w0bh[H3 * H],   g_w0bl[H3 * H];
__device__ __align__(16) __nv_bfloat16 g_embh[128 * EMB], g_embl[128 * EMB];
__device__ __align__(16) __nv_bfloat16 g_dech[B * INSZ], g_decl[B * INSZ];
__device__ __align__(16) __nv_bfloat16 g_a0h[2][B * H], g_a0l[2][B * H];
__device__ __align__(16) __nv_bfloat16 g_a1h[2][B * H], g_a1l[2][B * H];
__device__ __align__(16) __nv_bfloat16 g_a2h[2][B * H], g_a2l[2][B * H];

// ---------------- grid barrier (prologue only) ----------------
__device__ __forceinline__ void grid_bar()
{
    __syncthreads();
    if (threadIdx.x == 0) {
        __threadfence();
        volatile unsigned* php = &g_bar_phase;
        unsigned ph = *php;
        if (atomicAdd(&g_bar_count, 1u) == gridDim.x - 1u) {
            g_bar_count = 0u;
            __threadfence();
            atomicAdd(&g_bar_phase, 1u);
        } else {
            while (*php == ph) { __nanosleep(32); }
        }
        __threadfence();
    }
    __syncthreads();
}

// ---------------- dataflow sync ----------------
__device__ __forceinline__ void wait_ge(unsigned* c, unsigned tgt)
{
    if (threadIdx.x == 0) {
        volatile unsigned* vc = c;
        while (*vc < tgt) { __nanosleep(32); }
        __threadfence();
    }
    __syncthreads();
}
__device__ __forceinline__ void arrive(unsigned* c)
{
    if (threadIdx.x == 0) {
        __threadfence();
        atomicAdd(c, 1u);
    }
}

// ---------------- helpers ----------------
__device__ __forceinline__ float sigm(float x) { return 1.0f / (1.0f + __expf(-x)); }

__device__ __forceinline__ void bsplit(float x, __nv_bfloat16& hi, __nv_bfloat16& lo)
{
    hi = __float2bfloat16(x);
    lo = __float2bfloat16(x - __bfloat162float(hi));
}

__device__ __forceinline__ void mma16816(float* d, const uint32_t* a, const uint32_t* b)
{
    asm volatile(
        "mma.sync.aligned.m16n8k16.row.col.f32.bf16.bf16.f32 "
        "{%0,%1,%2,%3}, {%4,%5,%6,%7}, {%8,%9}, {%0,%1,%2,%3};"
        : "+f"(d[0]), "+f"(d[1]), "+f"(d[2]), "+f"(d[3])
        : "r"(a[0]), "r"(a[1]), "r"(a[2]), "r"(a[3]), "r"(b[0]), "r"(b[1]));
}
__device__ __forceinline__ void ldsm4(uint32_t& r0, uint32_t& r1, uint32_t& r2,
                                      uint32_t& r3, uint32_t a)
{
    asm volatile("ldmatrix.sync.aligned.m8n8.x4.shared.b16 {%0,%1,%2,%3}, [%4];"
                 : "=r"(r0), "=r"(r1), "=r"(r2), "=r"(r3) : "r"(a));
}
__device__ __forceinline__ void ldsm2(uint32_t& r0, uint32_t& r1, uint32_t a)
{
    asm volatile("ldmatrix.sync.aligned.m8n8.x2.shared.b16 {%0,%1}, [%2];"
                 : "=r"(r0), "=r"(r1) : "r"(a));
}
__device__ __forceinline__ void cpasync16(uint32_t dst, const void* src)
{
    asm volatile("cp.async.cg.shared.global [%0], [%1], 16;" :: "r"(dst), "l"(src));
}
#define CP_COMMIT() asm volatile("cp.async.commit_group;" ::: "memory")
#define CP_WAIT0()  asm volatile("cp.async.wait_group 0;" ::: "memory")

// ---------------- generic plain GEMM unit (prologue + logits) ----------------
struct MU {
    const __nv_bfloat16 *ah, *al, *wh, *wl;
    const float *bias, *cadd;
    float* C;
    int lda, ldw, ldadd, ldc, nch, mrows, ncols;
};

__device__ __forceinline__ MU mk_mu(
    const __nv_bfloat16* ah, const __nv_bfloat16* al, int lda,
    const __nv_bfloat16* wh, const __nv_bfloat16* wl, int ldw,
    const float* bias, const float* cadd, int ldadd,
    float* C, int ldc, int nch, int mrows, int ncols)
{
    MU u;
    u.ah = ah; u.al = al; u.wh = wh; u.wl = wl;
    u.bias = bias; u.cadd = cadd; u.C = C;
    u.lda = lda; u.ldw = ldw; u.ldadd = ldadd; u.ldc = ldc;
    u.nch = nch; u.mrows = mrows; u.ncols = ncols;
    return u;
}

template<int NF>
__device__ __noinline__ void mma_unit(const MU u, uint32_t smb)
{
    const int tid  = threadIdx.x;
    const int lane = tid & 31;
    const int w    = tid >> 5;
    const int wm   = w >> 2, wn = w & 3;
    const int gq   = lane >> 2, tq = lane & 3;
    constexpr int NP = NF / 2;

    float acc[2][NF][4];
#pragma unroll
    for (int i = 0; i < 2; i++)
#pragma unroll
        for (int j = 0; j < NF; j++)
#pragma unroll
            for (int k = 0; k < 4; k++) acc[i][j][k] = 0.0f;

    const int ar = tid >> 2, aq = tid & 3;
    const bool w2 = (NF == 6) && (tid < 256);
    const int w2i = 512 + tid;
    const int w2r = w2i >> 2, w2q = w2i & 3;
    const uint32_t soff  = (uint32_t)(ar * 80 + aq * 16);
    const uint32_t soff2 = (uint32_t)(w2r * 80 + w2q * 16);

    const uint32_t a_off = (uint32_t)((wm * 32 + (lane & 15)) * 80 + (lane >> 4) * 16);
    uint32_t b_off[NP];
#pragma unroll
    for (int p = 0; p < NP; p++)
        b_off[p] = (uint32_t)((wn * (NF * 8) + p * 16 + ((lane >> 4) << 3) + (lane & 7)) * 80
                              + ((lane >> 3) & 1) * 16);

#define G_ASYNC(c, buf) do { \
    const uint32_t bb = smb + (uint32_t)(buf) * BUFSTRIDE; \
    size_t goA = (size_t)ar * u.lda + (size_t)(c) * 32 + aq * 8; \
    size_t goW = (size_t)ar * u.ldw + (size_t)(c) * 32 + aq * 8; \
    cpasync16(bb + OFF_AXH + soff, u.ah + goA); \
    cpasync16(bb + OFF_AXL + soff, u.al + goA); \
    cpasync16(bb + OFF_WH + soff, u.wh + goW); \
    cpasync16(bb + OFF_WL + soff, u.wl + goW); \
    if (w2) { size_t go2 = (size_t)w2r * u.ldw + (size_t)(c) * 32 + w2q * 8; \
        cpasync16(bb + OFF_WH + soff2, u.wh + go2); \
        cpasync16(bb + OFF_WL + soff2, u.wl + go2); } \
    CP_COMMIT(); \
} while (0)

    G_ASYNC(0, 0);
    CP_WAIT0();
    __syncthreads();
    for (int c = 0; c < u.nch; c++) {
        if (c + 1 < u.nch) G_ASYNC(c + 1, (c + 1) & 1);
        const uint32_t bb = smb + (uint32_t)(c & 1) * BUFSTRIDE;
#pragma unroll
        for (int ks = 0; ks < 2; ks++) {
            const uint32_t ko = (uint32_t)(ks * 32);
            uint32_t bh[NF][2], bl[NF][2];
#pragma unroll
            for (int p = 0; p < NP; p++) {
                ldsm4(bh[2*p][0], bh[2*p][1], bh[2*p+1][0], bh[2*p+1][1],
                      bb + OFF_WH + b_off[p] + ko);
                ldsm4(bl[2*p][0], bl[2*p][1], bl[2*p+1][0], bl[2*p+1][1],
                      bb + OFF_WL + b_off[p] + ko);
            }
#pragma unroll
            for (int mf = 0; mf < 2; mf++) {
                uint32_t ah4[4], al4[4];
                ldsm4(ah4[0], ah4[1], ah4[2], ah4[3],
                      bb + OFF_AXH + a_off + (uint32_t)(mf * 1280) + ko);
                ldsm4(al4[0], al4[1], al4[2], al4[3],
                      bb + OFF_AXL + a_off + (uint32_t)(mf * 1280) + ko);
                // product-major: same-acc distance = NF
#pragma unroll
                for (int nf = 0; nf < NF; nf++) mma16816(acc[mf][nf], ah4, bh[nf]);
#pragma unroll
                for (int nf = 0; nf < NF; nf++) mma16816(acc[mf][nf], ah4, bl[nf]);
#pragma unroll
                for (int nf = 0; nf < NF; nf++) mma16816(acc[mf][nf], al4, bh[nf]);
            }
        }
        if (c + 1 < u.nch) CP_WAIT0();
        __syncthreads();
    }
#undef G_ASYNC

#pragma unroll
    for (int mf = 0; mf < 2; mf++) {
#pragma unroll
        for (int half = 0; half < 2; half++) {
            int m = wm * 32 + mf * 16 + gq + half * 8;
            if (m >= u.mrows) continue;
            float* crow = u.C + (size_t)m * u.ldc;
            const float* car = u.cadd ? u.cadd + (size_t)m * u.ldadd : nullptr;
#pragma unroll
            for (int nf = 0; nf < NF; nf++) {
#pragma unroll
                for (int e = 0; e < 2; e++) {
                    int col = wn * (NF * 8) + nf * 8 + 2 * tq + e;
                    if (col < u.ncols) {
                        float v = acc[mf][nf][half * 2 + e];
                        if (u.bias) v += u.bias[col];
                        if (car) v += car[col];
                        crow[col] = v;
                    }
                }
            }
        }
    }
    __syncthreads();
}

// ---------------- fused layer-1/2 unit ----------------
struct FU {
    const __nv_bfloat16 *xh, *xl, *hh, *hl;
    const __nv_bfloat16 *wh, *wl;
    const float* bc;
    float* hfp;
    __nv_bfloat16 *oah, *oal;
    int m0, j0;
};

__device__ __noinline__ void fused_l12(const FU u, uint32_t smb)
{
    const int tid  = threadIdx.x;
    const int lane = tid & 31;
    const int w    = tid >> 5;
    const int wm   = w >> 2, wn = w & 3;
    const int gq   = lane >> 2, tq = lane & 3;

    float acc[2][6][4];
#pragma unroll
    for (int i = 0; i < 2; i++)
#pragma unroll
        for (int j = 0; j < 6; j++)
#pragma unroll
            for (int k = 0; k < 4; k++) acc[i][j][k] = 0.0f;

    const int ar = tid >> 2, aq = tid & 3;
    const int w2i = 512 + (tid & 255);
    const int w2r = w2i >> 2, w2q = w2i & 3;
    const bool w2hi = (tid < 256);
    const uint32_t soff  = (uint32_t)(ar * 80 + aq * 16);
    const uint32_t soff2 = (uint32_t)(w2r * 80 + w2q * 16);

    const uint32_t a_off = (uint32_t)((wm * 32 + (lane & 15)) * 80 + (lane >> 4) * 16);
    uint32_t b_off[3];
#pragma unroll
    for (int p = 0; p < 3; p++)
        b_off[p] = (uint32_t)((wn * 48 + p * 16 + ((lane >> 4) << 3) + (lane & 7)) * 80
                              + ((lane >> 3) & 1) * 16);

#define F_ASYNC(c, buf) do { \
    const uint32_t bb = smb + (uint32_t)(buf) * BUFSTRIDE; \
    size_t goA = (size_t)(u.m0 + ar) * H + (size_t)(c) * 32 + aq * 8; \
    size_t goW = (size_t)ar * H + (size_t)(c) * 32 + aq * 8; \
    size_t go2 = (size_t)w2r * H + (size_t)(c) * 32 + w2q * 8; \
    cpasync16(bb + OFF_AXH + soff, u.xh + goA); \
    cpasync16(bb + OFF_AXL + soff, u.xl + goA); \
    cpasync16(bb + OFF_AHH + soff, u.hh + goA); \
    cpasync16(bb + OFF_AHL + soff, u.hl + goA); \
    cpasync16(bb + OFF_WH + soff, u.wh + goW); \
    cpasync16(bb + OFF_WL + soff, u.wl + goW); \
    cpasync16(bb + (w2hi ? OFF_WH : OFF_WL) + soff2, (w2hi ? u.wh : u.wl) + go2); \
    CP_COMMIT(); \
} while (0)

    F_ASYNC(0, 0);
    CP_WAIT0();
    __syncthreads();
    for (int c = 0; c < 32; c++) {
        if (c + 1 < 32) F_ASYNC(c + 1, (c + 1) & 1);
        const uint32_t bb = smb + (uint32_t)(c & 1) * BUFSTRIDE;
#pragma unroll
        for (int ks = 0; ks < 2; ks++) {
            const uint32_t ko = (uint32_t)(ks * 32);
            uint32_t bh[6][2], bl[6][2];
#pragma unroll
            for (int p = 0; p < 3; p++) {
                ldsm4(bh[2*p][0], bh[2*p][1], bh[2*p+1][0], bh[2*p+1][1],
                      bb + OFF_WH + b_off[p] + ko);
                ldsm4(bl[2*p][0], bl[2*p][1], bl[2*p+1][0], bl[2*p+1][1],
                      bb + OFF_WL + b_off[p] + ko);
            }
#pragma unroll
            for (int mf = 0; mf < 2; mf++) {
                const uint32_t am = a_off + (uint32_t)(mf * 1280) + ko;
                uint32_t xh4[4], xl4[4], hh4[4], hl4[4];
                ldsm4(xh4[0], xh4[1], xh4[2], xh4[3], bb + OFF_AXH + am);
                ldsm4(xl4[0], xl4[1], xl4[2], xl4[3], bb + OFF_AXL + am);
                ldsm4(hh4[0], hh4[1], hh4[2], hh4[3], bb + OFF_AHH + am);
                ldsm4(hl4[0], hl4[1], hl4[2], hl4[3], bb + OFF_AHL + am);
                // product-major: same-acc distance = 6
#pragma unroll
                for (int nf = 0; nf < 3; nf++) mma16816(acc[mf][nf],     xh4, bh[nf]);
#pragma unroll
                for (int nf = 3; nf < 6; nf++) mma16816(acc[mf][nf],     hh4, bh[nf]);
#pragma unroll
                for (int nf = 0; nf < 3; nf++) mma16816(acc[mf][nf],     xh4, bl[nf]);
#pragma unroll
                for (int nf = 3; nf < 6; nf++) mma16816(acc[mf][nf],     hh4, bl[nf]);
#pragma unroll
                for (int nf = 0; nf < 3; nf++) mma16816(acc[mf][nf],     xl4, bh[nf]);
#pragma unroll
                for (int nf = 3; nf < 6; nf++) mma16816(acc[mf][nf],     hl4, bh[nf]);
            }
        }
        if (c + 1 < 32) CP_WAIT0();
        __syncthreads();
    }
#undef F_ASYNC

#pragma unroll
    for (int e = 0; e < 2; e++) {
        const int j = u.j0 + wn * 8 + 2 * tq + e;
        const float* bcb = u.bc + wn * 48 + 2 * tq + e;
        float b0 = bcb[0], b1 = bcb[8], b2 = bcb[16];
        float b3 = bcb[24], b4 = bcb[32], b5 = bcb[40];
#pragma unroll
        for (int mf = 0; mf < 2; mf++) {
#pragma unroll
            for (int half = 0; half < 2; half++) {
                int m = u.m0 + wm * 32 + mf * 16 + gq + half * 8;
                int ai = half * 2 + e;
                float ir = acc[mf][0][ai] + b0;
                float iz = acc[mf][1][ai] + b1;
                float in_ = acc[mf][2][ai] + b2;
                float hr = acc[mf][3][ai] + b3;
                float hz = acc[mf][4][ai] + b4;
                float hn = acc[mf][5][ai] + b5;
                float r = sigm(ir + hr), zz = sigm(iz + hz);
                float n = tanhf(in_ + r * hn);
                size_t idx = (size_t)m * H + j;
                float hv = (1.0f - zz) * n + zz * u.hfp[idx];
                u.hfp[idx] = hv;
                bsplit(hv, u.oah[idx], u.oal[idx]);
            }
        }
    }
    __syncthreads();
}

// ---------------- fused layer-0 unit ----------------
struct F0 {
    const __nv_bfloat16 *hh, *hl;
    const __nv_bfloat16 *wh, *wl;
    const float* bc;
    const int* inp;
    int t, m0, j0;
    float* hfp;
    __nv_bfloat16 *oah, *oal;
};

__device__ __noinline__ void fused_l0(const F0 u, uint32_t smb)
{
    const int tid  = threadIdx.x;
    const int lane = tid & 31;
    const int w    = tid >> 5;
    const int wm   = w >> 3, wn = w & 7;
    const int gq   = lane >> 2, tq = lane & 3;

    float acc[2][3][4];
#pragma unroll
    for (int i = 0; i < 2; i++)
#pragma unroll
        for (int j = 0; j < 3; j++)
#pragma unroll
            for (int k = 0; k < 4; k++) acc[i][j][k] = 0.0f;

    const int ar = tid >> 2, aq = tid & 3;
    const bool aload = (tid < 256);
    const int w2i = 512 + (tid & 255);
    const int w2r = w2i >> 2, w2q = w2i & 3;
    const bool w2hi = (tid < 256);
    const uint32_t soff  = (uint32_t)(ar * 80 + aq * 16);
    const uint32_t soff2 = (uint32_t)(w2r * 80 + w2q * 16);

    const uint32_t a_off = (uint32_t)((wm * 32 + (lane & 15)) * 80 + (lane >> 4) * 16);
    const uint32_t b_off0 = (uint32_t)((wn * 24 + ((lane >> 4) << 3) + (lane & 7)) * 80
                                       + ((lane >> 3) & 1) * 16);
    const uint32_t b_off2 = (uint32_t)((wn * 24 + 16 + (lane & 7)) * 80
                                       + ((lane >> 3) & 1) * 16);

#define Z_ASYNC(c, buf) do { \
    const uint32_t bb = smb + (uint32_t)(buf) * BUFSTRIDE; \
    size_t goW = (size_t)ar * H + (size_t)(c) * 32 + aq * 8; \
    size_t go2 = (size_t)w2r * H + (size_t)(c) * 32 + w2q * 8; \
    if (aload) { size_t goA = (size_t)(u.m0 + ar) * H + (size_t)(c) * 32 + aq * 8; \
        cpasync16(bb + OFF_AXH + soff, u.hh + goA); \
        cpasync16(bb + OFF_AXL + soff, u.hl + goA); } \
    cpasync16(bb + OFF_WH + soff, u.wh + goW); \
    cpasync16(bb + OFF_WL + soff, u.wl + goW); \
    cpasync16(bb + (w2hi ? OFF_WH : OFF_WL) + soff2, (w2hi ? u.wh : u.wl) + go2); \
    CP_COMMIT(); \
} while (0)

    Z_ASYNC(0, 0);
    CP_WAIT0();
    __syncthreads();
    for (int c = 0; c < 32; c++) {
        if (c + 1 < 32) Z_ASYNC(c + 1, (c + 1) & 1);
        const uint32_t bb = smb + (uint32_t)(c & 1) * BUFSTRIDE;
#pragma unroll
        for (int ks = 0; ks < 2; ks++) {
            const uint32_t ko = (uint32_t)(ks * 32);
            uint32_t bh[3][2], bl[3][2];
            ldsm4(bh[0][0], bh[0][1], bh[1][0], bh[1][1], bb + OFF_WH + b_off0 + ko);
            ldsm4(bl[0][0], bl[0][1], bl[1][0], bl[1][1], bb + OFF_WL + b_off0 + ko);
            ldsm2(bh[2][0], bh[2][1], bb + OFF_WH + b_off2 + ko);
            ldsm2(bl[2][0], bl[2][1], bb + OFF_WL + b_off2 + ko);
            // load A for both mf, then product-major over all 6 accs
            uint32_t fh[2][4], fl[2][4];
#pragma unroll
            for (int mf = 0; mf < 2; mf++) {
                const uint32_t am = a_off + (uint32_t)(mf * 1280) + ko;
                ldsm4(fh[mf][0], fh[mf][1], fh[mf][2], fh[mf][3], bb + OFF_AXH + am);
                ldsm4(fl[mf][0], fl[mf][1], fl[mf][2], fl[mf][3], bb + OFF_AXL + am);
            }
#pragma unroll
            for (int mf = 0; mf < 2; mf++)
#pragma unroll
                for (int nf = 0; nf < 3; nf++) mma16816(acc[mf][nf], fh[mf], bh[nf]);
#pragma unroll
            for (int mf = 0; mf < 2; mf++)
#pragma unroll
                for (int nf = 0; nf < 3; nf++) mma16816(acc[mf][nf], fh[mf], bl[nf]);
#pragma unroll
            for (int mf = 0; mf < 2; mf++)
#pragma unroll
                for (int nf = 0; nf < 3; nf++) mma16816(acc[mf][nf], fl[mf], bh[nf]);
        }
        if (c + 1 < 32) CP_WAIT0();
        __syncthreads();
    }
#undef Z_ASYNC

#pragma unroll
    for (int e = 0; e < 2; e++) {
        const int j = u.j0 + wn * 8 + 2 * tq + e;
        const float* bcb = u.bc + wn * 24 + 2 * tq + e;
        float b0 = bcb[0], b1 = bcb[8], b2 = bcb[16];
#pragma unroll
        for (int mf = 0; mf < 2; mf++) {
#pragma unroll
            for (int half = 0; half < 2; half++) {
                int m = u.m0 + wm * 32 + mf * 16 + gq + half * 8;
                int ai = half * 2 + e;
                int tok = (u.t == 0) ? START_TOK : u.inp[m * S + u.t - 1];
                const float* tr = g_tokt + (size_t)tok * H3 + j;
                const float* gc = g_gi0c + (size_t)m * H3 + j;
                float ir = tr[0] + gc[0];
                float iz = tr[H] + gc[H];
                float in_ = tr[2 * H] + gc[2 * H];
                float hr = acc[mf][0][ai] + b0;
                float hz = acc[mf][1][ai] + b1;
                float hn = acc[mf][2][ai] + b2;
                float r = sigm(ir + hr), zz = sigm(iz + hz);
                float n = tanhf(in_ + r * hn);
                size_t idx = (size_t)m * H + j;
                float hv = (1.0f - zz) * n + zz * u.hfp[idx];
                u.hfp[idx] = hv;
                bsplit(hv, u.oah[idx], u.oal[idx]);
            }
        }
    }
    __syncthreads();
}

// ---------------- persistent kernel ----------------
__global__ __launch_bounds__(NTH, 1) void decoder_k(
    const int* __restrict__ inputs, const float* __restrict__ z,
    const float* __restrict__ cond, const float* __restrict__ emb,
    const float* __restrict__ i2h_w, const float* __restrict__ i2h_b,
    const float* __restrict__ out_w, const float* __restrict__ out_b,
    const float* __restrict__ wih0, const float* __restrict__ whh0,
    const float* __restrict__ bih0, const float* __restrict__ bhh0,
    const float* __restrict__ wih1, const float* __restrict__ whh1,
    const float* __restrict__ bih1, const float* __restrict__ bhh1,
    const float* __restrict__ wih2, const float* __restrict__ whh2,
    const float* __restrict__ bih2, const float* __restrict__ bhh2,
    float* __restrict__ out)
{
    extern __shared__ __align__(16) char smem[];
    uint32_t smb;
    asm("{ .reg .u64 t; cvta.to.shared.u64 t, %1; cvt.u32.u64 %0, t; }"
        : "=r"(smb) : "l"(smem));

    const int tid = threadIdx.x;
    const unsigned nb = gridDim.x;
    const int gid = blockIdx.x * NTH + tid;
    const int gstride = nb * NTH;

    if (blockIdx.x == 0 && tid == 0) {
        for (int i = 0; i < 8; i++) g_cntA[i] = 0u;
        for (int i = 0; i < 4; i++) { g_cntC[i] = 0u; g_cntE[i] = 0u; g_cntL[i] = 0u; }
    }

    // ---- P0: splits + gate-interleaved weight layouts ----
    for (int i = gid; i < 3072 * 1024; i += gstride) {
        int rd = i >> 10, k = i & 1023;
        int jb = rd / 192, r2 = rd - jb * 192;
        int jo = r2 / 24, r3 = r2 - jo * 24;
        int g = r3 >> 3, jr = r3 & 7;
        int j = jb * 64 + jo * 8 + jr;
        bsplit(whh0[(size_t)(g * H + j) * H + k], g_wc0h[i], g_wc0l[i]);
    }
    {
        const float* wi[2] = {wih1, wih2};
        const float* wr[2] = {whh1, whh2};
        __nv_bfloat16* dh[2] = {g_wc1h, g_wc2h};
        __nv_bfloat16* dl[2] = {g_wc1l, g_wc2l};
        for (int l = 0; l < 2; l++)
            for (int i = gid; i < 6144 * 1024; i += gstride) {
                int rd = i >> 10, k = i & 1023;
                int jb = rd / 192, r2 = rd - jb * 192;
                int jo = r2 / 48, r3 = r2 - jo * 48;
                int g = r3 >> 3, jr = r3 & 7;
                int j = jb * 32 + jo * 8 + jr;
                float v = (g < 3) ? wi[l][(size_t)(g * H + j) * H + k]
                                  : wr[l][(size_t)((g - 3) * H + j) * H + k];
                bsplit(v, dh[l][i], dl[l][i]);
            }
    }
    for (int i = gid; i < 3072; i += gstride) {
        int jb = i / 192, r2 = i - jb * 192;
        int jo = r2 / 24, r3 = r2 - jo * 24;
        int g = r3 >> 3, jr = r3 & 7;
        g_bc0[i] = bhh0[g * H + jb * 64 + jo * 8 + jr];
    }
    {
        const float* bi[2] = {bih1, bih2};
        const float* br[2] = {bhh1, bhh2};
        float* bd[2] = {g_bc1, g_bc2};
        for (int l = 0; l < 2; l++)
            for (int i = gid; i < 6144; i += gstride) {
                int jb = i / 192, r2 = i - jb * 192;
                int jo = r2 / 48, r3 = r2 - jo * 48;
                int g = r3 >> 3, jr = r3 & 7;
                int j = jb * 32 + jo * 8 + jr;
                bd[l][i] = (g < 3) ? bi[l][g * H + j] : br[l][(g - 3) * H + j];
            }
    }
    for (int i = gid; i < H * INSZ; i += gstride) bsplit(i2h_w[i], g_i2hh[i], g_i2hl[i]);
    for (int i = gid; i < H3 * EMB; i += gstride) {
        int r = i >> 9, c = i & 511;
        bsplit(wih0[(size_t)r * (EMB + INSZ) + c], g_w0ah[i], g_w0al[i]);
    }
    for (int i = gid; i < H3 * H; i += gstride) {
        int r = i >> 10, c = i & 1023;
        bsplit(wih0[(size_t)r * (EMB + INSZ) + EMB + c], g_w0bh[i], g_w0bl[i]);
    }
    for (int i = gid; i < 128 * EMB; i += gstride) {
        int r = i >> 9, c = i & 511;
        bsplit(r < V ? emb[r * EMB + c] : 0.0f, g_embh[i], g_embl[i]);
    }
    for (int i = gid; i < 128 * H; i += gstride) {
        int r = i >> 10, c = i & 1023;
        bsplit(r < V ? out_w[(size_t)r * (H + INSZ) + c] : 0.0f, g_owh[i], g_owl[i]);
        bsplit(r < V ? out_w[(size_t)r * (H + INSZ) + H + c] : 0.0f, g_ow2h[i], g_ow2l[i]);
    }
    for (int i = gid; i < B * INSZ; i += gstride) {
        int b = i >> 10, jx = i & 1023;
        float v = (jx < 512) ? z[b * 512 + jx] : cond[b * 512 + jx - 512];
        bsplit(v, g_dech[i], g_decl[i]);
    }
    grid_bar();

    // ---- P2: prologue GEMMs (116 units) ----
    for (int u = blockIdx.x; u < 116; u += nb) {
        if (u < 32) {
            int mt = u & 3, nt = u >> 2;
            mma_unit<4>(mk_mu(
                g_dech + (size_t)(mt * 128) * INSZ, g_decl + (size_t)(mt * 128) * INSZ, INSZ,
                g_i2hh + (size_t)(nt * 128) * INSZ, g_i2hl + (size_t)(nt * 128) * INSZ, INSZ,
                i2h_b + nt * 128, nullptr, 0,
                g_h0 + (size_t)(mt * 128) * H + nt * 128, H, 32, 128, 128), smb);
        } else if (u < 96) {
            int q = u - 32, mt = q & 3, nt = q >> 2;
            mma_unit<6>(mk_mu(
                g_dech + (size_t)(mt * 128) * INSZ, g_decl + (size_t)(mt * 128) * INSZ, INSZ,
                g_w0bh + (size_t)(nt * 192) * H, g_w0bl + (size_t)(nt * 192) * H, H,
                bih0 + nt * 192, nullptr, 0,
                g_gi0c + (size_t)(mt * 128) * H3 + nt * 192, H3, 32, 128, 192), smb);
        } else if (u < 112) {
            int nt = u - 96;
            mma_unit<6>(mk_mu(
                g_embh, g_embl, EMB,
                g_w0ah + (size_t)(nt * 192) * EMB, g_w0al + (size_t)(nt * 192) * EMB, EMB,
                nullptr, nullptr, 0,
                g_tokt + nt * 192, H3, 16, V, 192), smb);
        } else {
            int mt = u - 112;
            mma_unit<4>(mk_mu(
                g_dech + (size_t)(mt * 128) * INSZ, g_decl + (size_t)(mt * 128) * INSZ, INSZ,
                g_ow2h, g_ow2l, H,
                out_b, nullptr, 0,
                g_logc + (size_t)(mt * 128) * V, V, 32, 128, V), smb);
        }
    }
    grid_bar();

    // ---- P3: broadcast h_init + splits into buffer 0 ----
    for (int i = gid; i < B * H; i += gstride) {
        float v = g_h0[i];
        g_h1[i] = v; g_h2[i] = v;
        __nv_bfloat16 hi, lo;
        bsplit(v, hi, lo);
        g_a0h[0][i] = hi; g_a0l[0][i] = lo;
        g_a1h[0][i] = hi; g_a1l[0][i] = lo;
        g_a2h[0][i] = hi; g_a2l[0][i] = lo;
    }
    grid_bar();

    // ---- recurrent loop: barrier-free dataflow ----
    for (int t = 0; t < S; t++) {
        const int cur = t & 1, nxt = cur ^ 1;

        {
            const int U = 128 + (t > 0 ? 4 : 0);
            for (int u = blockIdx.x; u < U; u += nb) {
                if (u < 128) {
                    int mb = u & 7, jb = u >> 3;
                    if (t >= 1) wait_ge(&g_cntA[mb], 16u * (unsigned)t);
                    if (t >= 2) wait_ge(&g_cntC[mb >> 1], 32u * (unsigned)(t - 1));
                    F0 f;
                    f.hh = g_a0h[cur]; f.hl = g_a0l[cur];
                    f.wh = g_wc0h + (size_t)(jb * 192) * H;
                    f.wl = g_wc0l + (size_t)(jb * 192) * H;
                    f.bc = g_bc0 + jb * 192;
                    f.inp = inputs; f.t = t;
                    f.m0 = mb * 64; f.j0 = jb * 64;
                    f.hfp = g_h0; f.oah = g_a0h[nxt]; f.oal = g_a0l[nxt];
                    fused_l0(f, smb);
                    arrive(&g_cntA[mb]);
                } else {
                    int mt = u - 128;
                    wait_ge(&g_cntE[mt], 32u * (unsigned)t);
                    mma_unit<4>(mk_mu(
                        g_a2h[cur] + (size_t)(mt * 128) * H,
                        g_a2l[cur] + (size_t)(mt * 128) * H, H,
                        g_owh, g_owl, H,
                        nullptr, g_logc + (size_t)(mt * 128) * V, V,
                        out + (size_t)(mt * 128) * (S * V) + (size_t)(t - 1) * V,
                        S * V, 32, 128, V), smb);
                    arrive(&g_cntL[mt]);
                }
            }
        }

        for (int u = blockIdx.x; u < 128; u += nb) {
            int mb = u & 3, jb = u >> 2;
            wait_ge(&g_cntA[2 * mb], 16u * (unsigned)(t + 1));
            wait_ge(&g_cntA[2 * mb + 1], 16u * (unsigned)(t + 1));
            if (t >= 1) wait_ge(&g_cntC[mb], 32u * (unsigned)t);
            if (t >= 2) wait_ge(&g_cntE[mb], 32u * (unsigned)(t - 1));
            FU f;
            f.xh = g_a0h[nxt]; f.xl = g_a0l[nxt];
            f.hh = g_a1h[cur]; f.hl = g_a1l[cur];
            f.wh = g_wc1h + (size_t)(jb * 192) * H;
            f.wl = g_wc1l + (size_t)(jb * 192) * H;
            f.bc = g_bc1 + jb * 192;
            f.m0 = mb * 128; f.j0 = jb * 32;
            f.hfp = g_h1; f.oah = g_a1h[nxt]; f.oal = g_a1l[nxt];
            fused_l12(f, smb);
            arrive(&g_cntC[mb]);
        }

        for (int u = blockIdx.x; u < 128; u += nb) {
            int mb = u & 3, jb = u >> 2;
            wait_ge(&g_cntC[mb], 32u * (unsigned)(t + 1));
            if (t >= 1) wait_ge(&g_cntE[mb], 32u * (unsigned)t);
            if (t >= 2) wait_ge(&g_cntL[mb], (unsigned)(t - 1));
            FU f;
            f.xh = g_a1h[nxt]; f.xl = g_a1l[nxt];
            f.hh = g_a2h[cur]; f.hl = g_a2l[cur];
            f.wh = g_wc2h + (size_t)(jb * 192) * H;
            f.wl = g_wc2l + (size_t)(jb * 192) * H;
            f.bc = g_bc2 + jb * 192;
            f.m0 = mb * 128; f.j0 = jb * 32;
            f.hfp = g_h2; f.oah = g_a2h[nxt]; f.oal = g_a2l[nxt];
            fused_l12(f, smb);
            arrive(&g_cntE[mb]);
        }
    }

    // ---- final logits ----
    for (int u = blockIdx.x; u < 4; u += nb) {
        int mt = u;
        wait_ge(&g_cntE[mt], 32u * (unsigned)S);
        mma_unit<4>(mk_mu(
            g_a2h[S & 1] + (size_t)(mt * 128) * H,
            g_a2l[S & 1] + (size_t)(mt * 128) * H, H,
            g_owh, g_owl, H,
            nullptr, g_logc + (size_t)(mt * 128) * V, V,
            out + (size_t)(mt * 128) * (S * V) + (size_t)(S - 1) * V,
            S * V, 32, 128, V), smb);
    }
}

// ---------------- host ----------------
extern "C" void kernel_launch(void* const* d_in, const int* in_sizes, int n_in,
                              void* d_out, int out_size)
{
    (void)in_sizes; (void)n_in; (void)out_size;

    const int*   inputs = (const int*)  d_in[0];
    const float* z      = (const float*)d_in[1];
    const float* cond   = (const float*)d_in[2];
    const float* emb    = (const float*)d_in[4];
    const float* i2h_w  = (const float*)d_in[5];
    const float* i2h_b  = (const float*)d_in[6];
    const float* out_w  = (const float*)d_in[7];
    const float* out_b  = (const float*)d_in[8];
    const float* wih0 = (const float*)d_in[9];
    const float* whh0 = (const float*)d_in[10];
    const float* bih0 = (const float*)d_in[11];
    const float* bhh0 = (const float*)d_in[12];
    const float* wih1 = (const float*)d_in[13];
    const float* whh1 = (const float*)d_in[14];
    const float* bih1 = (const float*)d_in[15];
    const float* bhh1 = (const float*)d_in[16];
    const float* wih2 = (const float*)d_in[17];
    const float* whh2 = (const float*)d_in[18];
    const float* bih2 = (const float*)d_in[19];
    const float* bhh2 = (const float*)d_in[20];
    float* out = (float*)d_out;

    cudaFuncSetAttribute(decoder_k, cudaFuncAttributeMaxDynamicSharedMemorySize,
                         SMEM_TOTAL);

    int dev = 0;
    cudaGetDevice(&dev);
    int sms = 148;
    cudaDeviceGetAttribute(&sms, cudaDevAttrMultiProcessorCount, dev);
    int bpm = 1;
    cudaOccupancyMaxActiveBlocksPerMultiprocessor(&bpm, decoder_k, NTH, SMEM_TOTAL);
    if (bpm < 1) bpm = 1;

    decoder_k<<<sms * bpm, NTH, SMEM_TOTAL>>>(
        inputs, z, cond, emb, i2h_w, i2h_b, out_w, out_b,
        wih0, whh0, bih0, bhh0, wih1, whh1, bih1, bhh1,
        wih2, whh2, bih2, bhh2, out);
}

// round 15
// speedup vs baseline: 1.2834x; 1.2834x over previous
#include <cuda_runtime.h>
#include <cuda_fp16.h>
#include <cstdint>
#include <math.h>

#define B      512
#define S      200
#define H      1024
#define V      100
#define EMB    512
#define INSZ   1024
#define H3     3072
#define START_TOK 1
#define NTH    512

// smem (bytes): rows padded to 40 f16 (80B) for conflict-free LDSM
#define OFF_AXH 0u
#define OFF_AXL 10240u
#define OFF_AHH 20480u
#define OFF_AHL 30720u
#define OFF_W   40960u          // 192 rows x 80B = 15360
#define BUFSTRIDE 56320u
#define SMEM_TOTAL 112640

// ---------------- fp32 scratch ----------------
__device__ float g_h0[B * H];
__device__ float g_h1[B * H];
__device__ float g_h2[B * H];
__device__ float g_gi0c[B * H3];
__device__ float g_tokt[V * H3];
__device__ float g_logc[B * V];
__device__ float g_bc0[3072];
__device__ float g_bc1[6144];
__device__ float g_bc2[6144];
__device__ unsigned g_bar_count;
__device__ unsigned g_bar_phase;
__device__ unsigned g_cntA[8];
__device__ unsigned g_cntC[4];
__device__ unsigned g_cntE[4];
__device__ unsigned g_cntL[4];

// ---------------- fp16 weights (single) + fp16 activation splits ----------------
__device__ __align__(16) __half g_wc0[3072 * H];
__device__ __align__(16) __half g_wc1[6144 * H];
__device__ __align__(16) __half g_wc2[6144 * H];
__device__ __align__(16) __half g_ow[128 * H];
__device__ __align__(16) __half g_ow2[128 * H];
__device__ __align__(16) __half g_i2h[H * INSZ];
__device__ __align__(16) __half g_w0a[H3 * EMB];
__device__ __align__(16) __half g_w0b[H3 * H];
__device__ __align__(16) __half g_embh[128 * EMB], g_embl[128 * EMB];
__device__ __align__(16) __half g_dech[B * INSZ], g_decl[B * INSZ];
__device__ __align__(16) __half g_a0h[2][B * H], g_a0l[2][B * H];
__device__ __align__(16) __half g_a1h[2][B * H], g_a1l[2][B * H];
__device__ __align__(16) __half g_a2h[2][B * H], g_a2l[2][B * H];

// ---------------- grid barrier (prologue only) ----------------
__device__ __forceinline__ void grid_bar()
{
    __syncthreads();
    if (threadIdx.x == 0) {
        __threadfence();
        volatile unsigned* php = &g_bar_phase;
        unsigned ph = *php;
        if (atomicAdd(&g_bar_count, 1u) == gridDim.x - 1u) {
            g_bar_count = 0u;
            __threadfence();
            atomicAdd(&g_bar_phase, 1u);
        } else {
            while (*php == ph) { __nanosleep(32); }
        }
        __threadfence();
    }
    __syncthreads();
}

// ---------------- dataflow sync ----------------
__device__ __forceinline__ void wait_ge(unsigned* c, unsigned tgt)
{
    if (threadIdx.x == 0) {
        volatile unsigned* vc = c;
        while (*vc < tgt) { __nanosleep(32); }
        __threadfence();
    }
    __syncthreads();
}
__device__ __forceinline__ void arrive(unsigned* c)
{
    if (threadIdx.x == 0) {
        __threadfence();
        atomicAdd(c, 1u);
    }
}

// ---------------- helpers ----------------
__device__ __forceinline__ float sigm(float x) { return 1.0f / (1.0f + __expf(-x)); }

__device__ __forceinline__ void hsplit(float x, __half& hi, __half& lo)
{
    hi = __float2half_rn(x);
    lo = __float2half_rn(x - __half2float(hi));
}

__device__ __forceinline__ void mmaf16(float* d, const uint32_t* a, const uint32_t* b)
{
    asm volatile(
        "mma.sync.aligned.m16n8k16.row.col.f32.f16.f16.f32 "
        "{%0,%1,%2,%3}, {%4,%5,%6,%7}, {%8,%9}, {%0,%1,%2,%3};"
        : "+f"(d[0]), "+f"(d[1]), "+f"(d[2]), "+f"(d[3])
        : "r"(a[0]), "r"(a[1]), "r"(a[2]), "r"(a[3]), "r"(b[0]), "r"(b[1]));
}
__device__ __forceinline__ void ldsm4(uint32_t& r0, uint32_t& r1, uint32_t& r2,
                                      uint32_t& r3, uint32_t a)
{
    asm volatile("ldmatrix.sync.aligned.m8n8.x4.shared.b16 {%0,%1,%2,%3}, [%4];"
                 : "=r"(r0), "=r"(r1), "=r"(r2), "=r"(r3) : "r"(a));
}
__device__ __forceinline__ void ldsm2(uint32_t& r0, uint32_t& r1, uint32_t a)
{
    asm volatile("ldmatrix.sync.aligned.m8n8.x2.shared.b16 {%0,%1}, [%2];"
                 : "=r"(r0), "=r"(r1) : "r"(a));
}
__device__ __forceinline__ void cpasync16(uint32_t dst, const void* src)
{
    asm volatile("cp.async.cg.shared.global [%0], [%1], 16;" :: "r"(dst), "l"(src));
}
#define CP_COMMIT() asm volatile("cp.async.commit_group;" ::: "memory")
#define CP_WAIT0()  asm volatile("cp.async.wait_group 0;" ::: "memory")

// W loader: NROWS rows x 32 f16 each (4x16B segs/row), NROWS*4 segs total
template<int NROWS>
__device__ __forceinline__ void wload(uint32_t bb, const __half* w, int ldw, int c)
{
    constexpr int TOT = NROWS * 4;
#pragma unroll
    for (int i = 0; i < (TOT + NTH - 1) / NTH; i++) {
        int idx = threadIdx.x + i * NTH;
        if (TOT % NTH == 0 || idx < TOT) {
            int r = idx >> 2, q = idx & 3;
            cpasync16(bb + OFF_W + (uint32_t)(r * 80 + q * 16),
                      w + (size_t)r * ldw + (size_t)c * 32 + q * 8);
        }
    }
}

// ---------------- generic plain GEMM unit (prologue + logits) ----------------
struct MU {
    const __half *ah, *al, *w;
    const float *bias, *cadd;
    float* C;
    int lda, ldw, ldadd, ldc, nch, mrows, ncols;
};

__device__ __forceinline__ MU mk_mu(
    const __half* ah, const __half* al, int lda,
    const __half* w, int ldw,
    const float* bias, const float* cadd, int ldadd,
    float* C, int ldc, int nch, int mrows, int ncols)
{
    MU u;
    u.ah = ah; u.al = al; u.w = w;
    u.bias = bias; u.cadd = cadd; u.C = C;
    u.lda = lda; u.ldw = ldw; u.ldadd = ldadd; u.ldc = ldc;
    u.nch = nch; u.mrows = mrows; u.ncols = ncols;
    return u;
}

template<int NF>
__device__ __noinline__ void mma_unit(const MU u, uint32_t smb)
{
    const int tid  = threadIdx.x;
    const int lane = tid & 31;
    const int w    = tid >> 5;
    const int wm   = w >> 2, wn = w & 3;
    const int gq   = lane >> 2, tq = lane & 3;
    constexpr int NP = NF / 2;
    constexpr int WROWS = NF * 32;   // total B rows = 4 warps * NF*8

    float acc[2][NF][4];
#pragma unroll
    for (int i = 0; i < 2; i++)
#pragma unroll
        for (int j = 0; j < NF; j++)
#pragma unroll
            for (int k = 0; k < 4; k++) acc[i][j][k] = 0.0f;

    const int ar = tid >> 2, aq = tid & 3;
    const uint32_t soff = (uint32_t)(ar * 80 + aq * 16);

    const uint32_t a_off = (uint32_t)((wm * 32 + (lane & 15)) * 80 + (lane >> 4) * 16);
    uint32_t b_off[NP];
#pragma unroll
    for (int p = 0; p < NP; p++)
        b_off[p] = (uint32_t)((wn * (NF * 8) + p * 16 + ((lane >> 4) << 3) + (lane & 7)) * 80
                              + ((lane >> 3) & 1) * 16);

#define G_ASYNC(c, buf) do { \
    const uint32_t bb = smb + (uint32_t)(buf) * BUFSTRIDE; \
    size_t goA = (size_t)ar * u.lda + (size_t)(c) * 32 + aq * 8; \
    cpasync16(bb + OFF_AXH + soff, u.ah + goA); \
    cpasync16(bb + OFF_AXL + soff, u.al + goA); \
    wload<WROWS>(bb, u.w, u.ldw, (c)); \
    CP_COMMIT(); \
} while (0)

    G_ASYNC(0, 0);
    CP_WAIT0();
    __syncthreads();
    for (int c = 0; c < u.nch; c++) {
        if (c + 1 < u.nch) G_ASYNC(c + 1, (c + 1) & 1);
        const uint32_t bb = smb + (uint32_t)(c & 1) * BUFSTRIDE;
#pragma unroll
        for (int ks = 0; ks < 2; ks++) {
            const uint32_t ko = (uint32_t)(ks * 32);
            uint32_t bw[NF][2];
#pragma unroll
            for (int p = 0; p < NP; p++)
                ldsm4(bw[2*p][0], bw[2*p][1], bw[2*p+1][0], bw[2*p+1][1],
                      bb + OFF_W + b_off[p] + ko);
#pragma unroll
            for (int mf = 0; mf < 2; mf++) {
                uint32_t ah4[4], al4[4];
                ldsm4(ah4[0], ah4[1], ah4[2], ah4[3],
                      bb + OFF_AXH + a_off + (uint32_t)(mf * 1280) + ko);
                ldsm4(al4[0], al4[1], al4[2], al4[3],
                      bb + OFF_AXL + a_off + (uint32_t)(mf * 1280) + ko);
#pragma unroll
                for (int nf = 0; nf < NF; nf++) mmaf16(acc[mf][nf], ah4, bw[nf]);
#pragma unroll
                for (int nf = 0; nf < NF; nf++) mmaf16(acc[mf][nf], al4, bw[nf]);
            }
        }
        if (c + 1 < u.nch) CP_WAIT0();
        __syncthreads();
    }
#undef G_ASYNC

#pragma unroll
    for (int mf = 0; mf < 2; mf++) {
#pragma unroll
        for (int half = 0; half < 2; half++) {
            int m = wm * 32 + mf * 16 + gq + half * 8;
            if (m >= u.mrows) continue;
            float* crow = u.C + (size_t)m * u.ldc;
            const float* car = u.cadd ? u.cadd + (size_t)m * u.ldadd : nullptr;
#pragma unroll
            for (int nf = 0; nf < NF; nf++) {
#pragma unroll
                for (int e = 0; e < 2; e++) {
                    int col = wn * (NF * 8) + nf * 8 + 2 * tq + e;
                    if (col < u.ncols) {
                        float v = acc[mf][nf][half * 2 + e];
                        if (u.bias) v += u.bias[col];
                        if (car) v += car[col];
                        crow[col] = v;
                    }
                }
            }
        }
    }
    __syncthreads();
}

// ---------------- fused layer-1/2 unit ----------------
struct FU {
    const __half *xh, *xl, *hh, *hl;
    const __half *w;                 // 192 rows x 1024
    const float* bc;
    float* hfp;
    __half *oah, *oal;
    int m0, j0;
};

__device__ __noinline__ void fused_l12(const FU u, uint32_t smb)
{
    const int tid  = threadIdx.x;
    const int lane = tid & 31;
    const int w    = tid >> 5;
    const int wm   = w >> 2, wn = w & 3;
    const int gq   = lane >> 2, tq = lane & 3;

    float acc[2][6][4];
#pragma unroll
    for (int i = 0; i < 2; i++)
#pragma unroll
        for (int j = 0; j < 6; j++)
#pragma unroll
            for (int k = 0; k < 4; k++) acc[i][j][k] = 0.0f;

    const int ar = tid >> 2, aq = tid & 3;
    const uint32_t soff = (uint32_t)(ar * 80 + aq * 16);

    const uint32_t a_off = (uint32_t)((wm * 32 + (lane & 15)) * 80 + (lane >> 4) * 16);
    uint32_t b_off[3];
#pragma unroll
    for (int p = 0; p < 3; p++)
        b_off[p] = (uint32_t)((wn * 48 + p * 16 + ((lane >> 4) << 3) + (lane & 7)) * 80
                              + ((lane >> 3) & 1) * 16);

#define F_ASYNC(c, buf) do { \
    const uint32_t bb = smb + (uint32_t)(buf) * BUFSTRIDE; \
    size_t goA = (size_t)(u.m0 + ar) * H + (size_t)(c) * 32 + aq * 8; \
    cpasync16(bb + OFF_AXH + soff, u.xh + goA); \
    cpasync16(bb + OFF_AXL + soff, u.xl + goA); \
    cpasync16(bb + OFF_AHH + soff, u.hh + goA); \
    cpasync16(bb + OFF_AHL + soff, u.hl + goA); \
    wload<192>(bb, u.w, H, (c)); \
    CP_COMMIT(); \
} while (0)

    F_ASYNC(0, 0);
    CP_WAIT0();
    __syncthreads();
    for (int c = 0; c < 32; c++) {
        if (c + 1 < 32) F_ASYNC(c + 1, (c + 1) & 1);
        const uint32_t bb = smb + (uint32_t)(c & 1) * BUFSTRIDE;
#pragma unroll
        for (int ks = 0; ks < 2; ks++) {
            const uint32_t ko = (uint32_t)(ks * 32);
            uint32_t bw[6][2];
#pragma unroll
            for (int p = 0; p < 3; p++)
                ldsm4(bw[2*p][0], bw[2*p][1], bw[2*p+1][0], bw[2*p+1][1],
                      bb + OFF_W + b_off[p] + ko);
#pragma unroll
            for (int mf = 0; mf < 2; mf++) {
                const uint32_t am = a_off + (uint32_t)(mf * 1280) + ko;
                uint32_t xh4[4], xl4[4], hh4[4], hl4[4];
                ldsm4(xh4[0], xh4[1], xh4[2], xh4[3], bb + OFF_AXH + am);
                ldsm4(xl4[0], xl4[1], xl4[2], xl4[3], bb + OFF_AXL + am);
                ldsm4(hh4[0], hh4[1], hh4[2], hh4[3], bb + OFF_AHH + am);
                ldsm4(hl4[0], hl4[1], hl4[2], hl4[3], bb + OFF_AHL + am);
#pragma unroll
                for (int nf = 0; nf < 3; nf++) mmaf16(acc[mf][nf], xh4, bw[nf]);
#pragma unroll
                for (int nf = 3; nf < 6; nf++) mmaf16(acc[mf][nf], hh4, bw[nf]);
#pragma unroll
                for (int nf = 0; nf < 3; nf++) mmaf16(acc[mf][nf], xl4, bw[nf]);
#pragma unroll
                for (int nf = 3; nf < 6; nf++) mmaf16(acc[mf][nf], hl4, bw[nf]);
            }
        }
        if (c + 1 < 32) CP_WAIT0();
        __syncthreads();
    }
#undef F_ASYNC

#pragma unroll
    for (int e = 0; e < 2; e++) {
        const int j = u.j0 + wn * 8 + 2 * tq + e;
        const float* bcb = u.bc + wn * 48 + 2 * tq + e;
        float b0 = bcb[0], b1 = bcb[8], b2 = bcb[16];
        float b3 = bcb[24], b4 = bcb[32], b5 = bcb[40];
#pragma unroll
        for (int mf = 0; mf < 2; mf++) {
#pragma unroll
            for (int half = 0; half < 2; half++) {
                int m = u.m0 + wm * 32 + mf * 16 + gq + half * 8;
                int ai = half * 2 + e;
                float ir = acc[mf][0][ai] + b0;
                float iz = acc[mf][1][ai] + b1;
                float in_ = acc[mf][2][ai] + b2;
                float hr = acc[mf][3][ai] + b3;
                float hz = acc[mf][4][ai] + b4;
                float hn = acc[mf][5][ai] + b5;
                float r = sigm(ir + hr), zz = sigm(iz + hz);
                float n = tanhf(in_ + r * hn);
                size_t idx = (size_t)m * H + j;
                float hv = (1.0f - zz) * n + zz * u.hfp[idx];
                u.hfp[idx] = hv;
                hsplit(hv, u.oah[idx], u.oal[idx]);
            }
        }
    }
    __syncthreads();
}

// ---------------- fused layer-0 unit ----------------
struct F0 {
    const __half *hh, *hl;
    const __half *w;                 // 192 rows x 1024
    const float* bc;
    const int* inp;
    int t, m0, j0;
    float* hfp;
    __half *oah, *oal;
};

__device__ __noinline__ void fused_l0(const F0 u, uint32_t smb)
{
    const int tid  = threadIdx.x;
    const int lane = tid & 31;
    const int w    = tid >> 5;
    const int wm   = w >> 3, wn = w & 7;
    const int gq   = lane >> 2, tq = lane & 3;

    float acc[2][3][4];
#pragma unroll
    for (int i = 0; i < 2; i++)
#pragma unroll
        for (int j = 0; j < 3; j++)
#pragma unroll
            for (int k = 0; k < 4; k++) acc[i][j][k] = 0.0f;

    const int ar = tid >> 2, aq = tid & 3;
    const uint32_t soff = (uint32_t)(ar * 80 + aq * 16);

    const uint32_t a_off = (uint32_t)((wm * 32 + (lane & 15)) * 80 + (lane >> 4) * 16);
    const uint32_t b_off0 = (uint32_t)((wn * 24 + ((lane >> 4) << 3) + (lane & 7)) * 80
                                       + ((lane >> 3) & 1) * 16);
    const uint32_t b_off2 = (uint32_t)((wn * 24 + 16 + (lane & 7)) * 80
                                       + ((lane >> 3) & 1) * 16);

#define Z_ASYNC(c, buf) do { \
    const uint32_t bb = smb + (uint32_t)(buf) * BUFSTRIDE; \
    if (tid < 256) { \
        size_t goA = (size_t)(u.m0 + ar) * H + (size_t)(c) * 32 + aq * 8; \
        cpasync16(bb + OFF_AXH + soff, u.hh + goA); \
        cpasync16(bb + OFF_AXL + soff, u.hl + goA); } \
    wload<192>(bb, u.w, H, (c)); \
    CP_COMMIT(); \
} while (0)

    Z_ASYNC(0, 0);
    CP_WAIT0();
    __syncthreads();
    for (int c = 0; c < 32; c++) {
        if (c + 1 < 32) Z_ASYNC(c + 1, (c + 1) & 1);
        const uint32_t bb = smb + (uint32_t)(c & 1) * BUFSTRIDE;
#pragma unroll
        for (int ks = 0; ks < 2; ks++) {
            const uint32_t ko = (uint32_t)(ks * 32);
            uint32_t bw[3][2];
            ldsm4(bw[0][0], bw[0][1], bw[1][0], bw[1][1], bb + OFF_W + b_off0 + ko);
            ldsm2(bw[2][0], bw[2][1], bb + OFF_W + b_off2 + ko);
            uint32_t fh[2][4], fl[2][4];
#pragma unroll
            for (int mf = 0; mf < 2; mf++) {
                const uint32_t am = a_off + (uint32_t)(mf * 1280) + ko;
                ldsm4(fh[mf][0], fh[mf][1], fh[mf][2], fh[mf][3], bb + OFF_AXH + am);
                ldsm4(fl[mf][0], fl[mf][1], fl[mf][2], fl[mf][3], bb + OFF_AXL + am);
            }
#pragma unroll
            for (int mf = 0; mf < 2; mf++)
#pragma unroll
                for (int nf = 0; nf < 3; nf++) mmaf16(acc[mf][nf], fh[mf], bw[nf]);
#pragma unroll
            for (int mf = 0; mf < 2; mf++)
#pragma unroll
                for (int nf = 0; nf < 3; nf++) mmaf16(acc[mf][nf], fl[mf], bw[nf]);
        }
        if (c + 1 < 32) CP_WAIT0();
        __syncthreads();
    }
#undef Z_ASYNC

#pragma unroll
    for (int e = 0; e < 2; e++) {
        const int j = u.j0 + wn * 8 + 2 * tq + e;
        const float* bcb = u.bc + wn * 24 + 2 * tq + e;
        float b0 = bcb[0], b1 = bcb[8], b2 = bcb[16];
#pragma unroll
        for (int mf = 0; mf < 2; mf++) {
#pragma unroll
            for (int half = 0; half < 2; half++) {
                int m = u.m0 + wm * 32 + mf * 16 + gq + half * 8;
                int ai = half * 2 + e;
                int tok = (u.t == 0) ? START_TOK : u.inp[m * S + u.t - 1];
                const float* tr = g_tokt + (size_t)tok * H3 + j;
                const float* gc = g_gi0c + (size_t)m * H3 + j;
                float ir = tr[0] + gc[0];
                float iz = tr[H] + gc[H];
                float in_ = tr[2 * H] + gc[2 * H];
                float hr = acc[mf][0][ai] + b0;
                float hz = acc[mf][1][ai] + b1;
                float hn = acc[mf][2][ai] + b2;
                float r = sigm(ir + hr), zz = sigm(iz + hz);
                float n = tanhf(in_ + r * hn);
                size_t idx = (size_t)m * H + j;
                float hv = (1.0f - zz) * n + zz * u.hfp[idx];
                u.hfp[idx] = hv;
                hsplit(hv, u.oah[idx], u.oal[idx]);
            }
        }
    }
    __syncthreads();
}

// ---------------- persistent kernel ----------------
__global__ __launch_bounds__(NTH, 1) void decoder_k(
    const int* __restrict__ inputs, const float* __restrict__ z,
    const float* __restrict__ cond, const float* __restrict__ emb,
    const float* __restrict__ i2h_w, const float* __restrict__ i2h_b,
    const float* __restrict__ out_w, const float* __restrict__ out_b,
    const float* __restrict__ wih0, const float* __restrict__ whh0,
    const float* __restrict__ bih0, const float* __restrict__ bhh0,
    const float* __restrict__ wih1, const float* __restrict__ whh1,
    const float* __restrict__ bih1, const float* __restrict__ bhh1,
    const float* __restrict__ wih2, const float* __restrict__ whh2,
    const float* __restrict__ bih2, const float* __restrict__ bhh2,
    float* __restrict__ out)
{
    extern __shared__ __align__(16) char smem[];
    uint32_t smb;
    asm("{ .reg .u64 t; cvta.to.shared.u64 t, %1; cvt.u32.u64 %0, t; }"
        : "=r"(smb) : "l"(smem));

    const int tid = threadIdx.x;
    const unsigned nb = gridDim.x;
    const int gid = blockIdx.x * NTH + tid;
    const int gstride = nb * NTH;

    if (blockIdx.x == 0 && tid == 0) {
        for (int i = 0; i < 8; i++) g_cntA[i] = 0u;
        for (int i = 0; i < 4; i++) { g_cntC[i] = 0u; g_cntE[i] = 0u; g_cntL[i] = 0u; }
    }

    // ---- P0: weight conversions + gate-interleaved layouts ----
    for (int i = gid; i < 3072 * 1024; i += gstride) {
        int rd = i >> 10, k = i & 1023;
        int jb = rd / 192, r2 = rd - jb * 192;
        int jo = r2 / 24, r3 = r2 - jo * 24;
        int g = r3 >> 3, jr = r3 & 7;
        int j = jb * 64 + jo * 8 + jr;
        g_wc0[i] = __float2half_rn(whh0[(size_t)(g * H + j) * H + k]);
    }
    {
        const float* wi[2] = {wih1, wih2};
        const float* wr[2] = {whh1, whh2};
        __half* dw[2] = {g_wc1, g_wc2};
        for (int l = 0; l < 2; l++)
            for (int i = gid; i < 6144 * 1024; i += gstride) {
                int rd = i >> 10, k = i & 1023;
                int jb = rd / 192, r2 = rd - jb * 192;
                int jo = r2 / 48, r3 = r2 - jo * 48;
                int g = r3 >> 3, jr = r3 & 7;
                int j = jb * 32 + jo * 8 + jr;
                float v = (g < 3) ? wi[l][(size_t)(g * H + j) * H + k]
                                  : wr[l][(size_t)((g - 3) * H + j) * H + k];
                dw[l][i] = __float2half_rn(v);
            }
    }
    for (int i = gid; i < 3072; i += gstride) {
        int jb = i / 192, r2 = i - jb * 192;
        int jo = r2 / 24, r3 = r2 - jo * 24;
        int g = r3 >> 3, jr = r3 & 7;
        g_bc0[i] = bhh0[g * H + jb * 64 + jo * 8 + jr];
    }
    {
        const float* bi[2] = {bih1, bih2};
        const float* br[2] = {bhh1, bhh2};
        float* bd[2] = {g_bc1, g_bc2};
        for (int l = 0; l < 2; l++)
            for (int i = gid; i < 6144; i += gstride) {
                int jb = i / 192, r2 = i - jb * 192;
                int jo = r2 / 48, r3 = r2 - jo * 48;
                int g = r3 >> 3, jr = r3 & 7;
                int j = jb * 32 + jo * 8 + jr;
                bd[l][i] = (g < 3) ? bi[l][g * H + j] : br[l][(g - 3) * H + j];
            }
    }
    for (int i = gid; i < H * INSZ; i += gstride) g_i2h[i] = __float2half_rn(i2h_w[i]);
    for (int i = gid; i < H3 * EMB; i += gstride) {
        int r = i >> 9, c = i & 511;
        g_w0a[i] = __float2half_rn(wih0[(size_t)r * (EMB + INSZ) + c]);
    }
    for (int i = gid; i < H3 * H; i += gstride) {
        int r = i >> 10, c = i & 1023;
        g_w0b[i] = __float2half_rn(wih0[(size_t)r * (EMB + INSZ) + EMB + c]);
    }
    for (int i = gid; i < 128 * EMB; i += gstride) {
        int r = i >> 9, c = i & 511;
        hsplit(r < V ? emb[r * EMB + c] : 0.0f, g_embh[i], g_embl[i]);
    }
    for (int i = gid; i < 128 * H; i += gstride) {
        int r = i >> 10, c = i & 1023;
        g_ow[i]  = __float2half_rn(r < V ? out_w[(size_t)r * (H + INSZ) + c] : 0.0f);
        g_ow2[i] = __float2half_rn(r < V ? out_w[(size_t)r * (H + INSZ) + H + c] : 0.0f);
    }
    for (int i = gid; i < B * INSZ; i += gstride) {
        int b = i >> 10, jx = i & 1023;
        float v = (jx < 512) ? z[b * 512 + jx] : cond[b * 512 + jx - 512];
        hsplit(v, g_dech[i], g_decl[i]);
    }
    grid_bar();

    // ---- P2: prologue GEMMs (116 units) ----
    for (int u = blockIdx.x; u < 116; u += nb) {
        if (u < 32) {
            int mt = u & 3, nt = u >> 2;
            mma_unit<4>(mk_mu(
                g_dech + (size_t)(mt * 128) * INSZ, g_decl + (size_t)(mt * 128) * INSZ, INSZ,
                g_i2h + (size_t)(nt * 128) * INSZ, INSZ,
                i2h_b + nt * 128, nullptr, 0,
                g_h0 + (size_t)(mt * 128) * H + nt * 128, H, 32, 128, 128), smb);
        } else if (u < 96) {
            int q = u - 32, mt = q & 3, nt = q >> 2;
            mma_unit<6>(mk_mu(
                g_dech + (size_t)(mt * 128) * INSZ, g_decl + (size_t)(mt * 128) * INSZ, INSZ,
                g_w0b + (size_t)(nt * 192) * H, H,
                bih0 + nt * 192, nullptr, 0,
                g_gi0c + (size_t)(mt * 128) * H3 + nt * 192, H3, 32, 128, 192), smb);
        } else if (u < 112) {
            int nt = u - 96;
            mma_unit<6>(mk_mu(
                g_embh, g_embl, EMB,
                g_w0a + (size_t)(nt * 192) * EMB, EMB,
                nullptr, nullptr, 0,
                g_tokt + nt * 192, H3, 16, V, 192), smb);
        } else {
            int mt = u - 112;
            mma_unit<4>(mk_mu(
                g_dech + (size_t)(mt * 128) * INSZ, g_decl + (size_t)(mt * 128) * INSZ, INSZ,
                g_ow2, H,
                out_b, nullptr, 0,
                g_logc + (size_t)(mt * 128) * V, V, 32, 128, V), smb);
        }
    }
    grid_bar();

    // ---- P3: broadcast h_init + splits into buffer 0 ----
    for (int i = gid; i < B * H; i += gstride) {
        float v = g_h0[i];
        g_h1[i] = v; g_h2[i] = v;
        __half hi, lo;
        hsplit(v, hi, lo);
        g_a0h[0][i] = hi; g_a0l[0][i] = lo;
        g_a1h[0][i] = hi; g_a1l[0][i] = lo;
        g_a2h[0][i] = hi; g_a2l[0][i] = lo;
    }
    grid_bar();

    // ---- recurrent loop: barrier-free dataflow ----
    for (int t = 0; t < S; t++) {
        const int cur = t & 1, nxt = cur ^ 1;

        {
            const int U = 128 + (t > 0 ? 4 : 0);
            for (int u = blockIdx.x; u < U; u += nb) {
                if (u < 128) {
                    int mb = u & 7, jb = u >> 3;
                    if (t >= 1) wait_ge(&g_cntA[mb], 16u * (unsigned)t);
                    if (t >= 2) wait_ge(&g_cntC[mb >> 1], 32u * (unsigned)(t - 1));
                    F0 f;
                    f.hh = g_a0h[cur]; f.hl = g_a0l[cur];
                    f.w = g_wc0 + (size_t)(jb * 192) * H;
                    f.bc = g_bc0 + jb * 192;
                    f.inp = inputs; f.t = t;
                    f.m0 = mb * 64; f.j0 = jb * 64;
                    f.hfp = g_h0; f.oah = g_a0h[nxt]; f.oal = g_a0l[nxt];
                    fused_l0(f, smb);
                    arrive(&g_cntA[mb]);
                } else {
                    int mt = u - 128;
                    wait_ge(&g_cntE[mt], 32u * (unsigned)t);
                    mma_unit<4>(mk_mu(
                        g_a2h[cur] + (size_t)(mt * 128) * H,
                        g_a2l[cur] + (size_t)(mt * 128) * H, H,
                        g_ow, H,
                        nullptr, g_logc + (size_t)(mt * 128) * V, V,
                        out + (size_t)(mt * 128) * (S * V) + (size_t)(t - 1) * V,
                        S * V, 32, 128, V), smb);
                    arrive(&g_cntL[mt]);
                }
            }
        }

        for (int u = blockIdx.x; u < 128; u += nb) {
            int mb = u & 3, jb = u >> 2;
            wait_ge(&g_cntA[2 * mb], 16u * (unsigned)(t + 1));
            wait_ge(&g_cntA[2 * mb + 1], 16u * (unsigned)(t + 1));
            if (t >= 1) wait_ge(&g_cntC[mb], 32u * (unsigned)t);
            if (t >= 2) wait_ge(&g_cntE[mb], 32u * (unsigned)(t - 1));
            FU f;
            f.xh = g_a0h[nxt]; f.xl = g_a0l[nxt];
            f.hh = g_a1h[cur]; f.hl = g_a1l[cur];
            f.w = g_wc1 + (size_t)(jb * 192) * H;
            f.bc = g_bc1 + jb * 192;
            f.m0 = mb * 128; f.j0 = jb * 32;
            f.hfp = g_h1; f.oah = g_a1h[nxt]; f.oal = g_a1l[nxt];
            fused_l12(f, smb);
            arrive(&g_cntC[mb]);
        }

        for (int u = blockIdx.x; u < 128; u += nb) {
            int mb = u & 3, jb = u >> 2;
            wait_ge(&g_cntC[mb], 32u * (unsigned)(t + 1));
            if (t >= 1) wait_ge(&g_cntE[mb], 32u * (unsigned)t);
            if (t >= 2) wait_ge(&g_cntL[mb], (unsigned)(t - 1));
            FU f;
            f.xh = g_a1h[nxt]; f.xl = g_a1l[nxt];
            f.hh = g_a2h[cur]; f.hl = g_a2l[cur];
            f.w = g_wc2 + (size_t)(jb * 192) * H;
            f.bc = g_bc2 + jb * 192;
            f.m0 = mb * 128; f.j0 = jb * 32;
            f.hfp = g_h2; f.oah = g_a2h[nxt]; f.oal = g_a2l[nxt];
            fused_l12(f, smb);
            arrive(&g_cntE[mb]);
        }
    }

    // ---- final logits ----
    for (int u = blockIdx.x; u < 4; u += nb) {
        int mt = u;
        wait_ge(&g_cntE[mt], 32u * (unsigned)S);
        mma_unit<4>(mk_mu(
            g_a2h[S & 1] + (size_t)(mt * 128) * H,
            g_a2l[S & 1] + (size_t)(mt * 128) * H, H,
            g_ow, H,
            nullptr, g_logc + (size_t)(mt * 128) * V, V,
            out + (size_t)(mt * 128) * (S * V) + (size_t)(S - 1) * V,
            S * V, 32, 128, V), smb);
    }
}

// ---------------- host ----------------
extern "C" void kernel_launch(void* const* d_in, const int* in_sizes, int n_in,
                              void* d_out, int out_size)
{
    (void)in_sizes; (void)n_in; (void)out_size;

    const int*   inputs = (const int*)  d_in[0];
    const float* z      = (const float*)d_in[1];
    const float* cond   = (const float*)d_in[2];
    const float* emb    = (const float*)d_in[4];
    const float* i2h_w  = (const float*)d_in[5];
    const float* i2h_b  = (const float*)d_in[6];
    const float* out_w  = (const float*)d_in[7];
    const float* out_b  = (const float*)d_in[8];
    const float* wih0 = (const float*)d_in[9];
    const float* whh0 = (const float*)d_in[10];
    const float* bih0 = (const float*)d_in[11];
    const float* bhh0 = (const float*)d_in[12];
    const float* wih1 = (const float*)d_in[13];
    const float* whh1 = (const float*)d_in[14];
    const float* bih1 = (const float*)d_in[15];
    const float* bhh1 = (const float*)d_in[16];
    const float* wih2 = (const float*)d_in[17];
    const float* whh2 = (const float*)d_in[18];
    const float* bih2 = (const float*)d_in[19];
    const float* bhh2 = (const float*)d_in[20];
    float* out = (float*)d_out;

    cudaFuncSetAttribute(decoder_k, cudaFuncAttributeMaxDynamicSharedMemorySize,
                         SMEM_TOTAL);

    int dev = 0;
    cudaGetDevice(&dev);
    int sms = 148;
    cudaDeviceGetAttribute(&sms, cudaDevAttrMultiProcessorCount, dev);
    int bpm = 1;
    cudaOccupancyMaxActiveBlocksPerMultiprocessor(&bpm, decoder_k, NTH, SMEM_TOTAL);
    if (bpm < 1) bpm = 1;

    decoder_k<<<sms * bpm, NTH, SMEM_TOTAL>>>(
        inputs, z, cond, emb, i2h_w, i2h_b, out_w, out_b,
        wih0, whh0, bih0, bhh0, wih1, whh1, bih1, bhh1,
        wih2, whh2, bih2, bhh2, out);
}

// round 16
// speedup vs baseline: 2.1743x; 1.6942x over previous
#include <cuda_runtime.h>
#include <cuda_fp16.h>
#include <cstdint>
#include <math.h>

#define B      512
#define S      200
#define H      1024
#define V      100
#define EMB    512
#define INSZ   1024
#define H3     3072
#define START_TOK 1
#define NTH    512

// smem (bytes): rows padded to 40 f16 (80B) for conflict-free LDSM
#define OFF_AX  0u              // 128 rows (A / x)
#define OFF_AH  10240u          // 128 rows (h)
#define OFF_W   20480u          // 192 rows
#define BUFSTRIDE 35840u
#define SMEM_TOTAL 71680

// ---------------- fp32 scratch ----------------
__device__ float g_h0[B * H];
__device__ float g_h1[B * H];
__device__ float g_h2[B * H];
__device__ float g_gi0c[B * H3];
__device__ float g_tokt[V * H3];
__device__ float g_logc[B * V];
__device__ float g_bc0[3072];
__device__ float g_bc1[6144];
__device__ float g_bc2[6144];
__device__ unsigned g_bar_count;
__device__ unsigned g_bar_phase;
__device__ unsigned g_cntA[8];
__device__ unsigned g_cntC[4];
__device__ unsigned g_cntE[4];
__device__ unsigned g_cntL[4];

// ---------------- fp16 weights + single fp16 activations ----------------
__device__ __align__(16) __half g_wc0[3072 * H];
__device__ __align__(16) __half g_wc1[6144 * H];
__device__ __align__(16) __half g_wc2[6144 * H];
__device__ __align__(16) __half g_ow[128 * H];
__device__ __align__(16) __half g_ow2[128 * H];
__device__ __align__(16) __half g_i2h[H * INSZ];
__device__ __align__(16) __half g_w0a[H3 * EMB];
__device__ __align__(16) __half g_w0b[H3 * H];
__device__ __align__(16) __half g_emb[128 * EMB];
__device__ __align__(16) __half g_dec[B * INSZ];
__device__ __align__(16) __half g_a0[2][B * H];
__device__ __align__(16) __half g_a1[2][B * H];
__device__ __align__(16) __half g_a2[2][B * H];

// ---------------- grid barrier (prologue only) ----------------
__device__ __forceinline__ void grid_bar()
{
    __syncthreads();
    if (threadIdx.x == 0) {
        __threadfence();
        volatile unsigned* php = &g_bar_phase;
        unsigned ph = *php;
        if (atomicAdd(&g_bar_count, 1u) == gridDim.x - 1u) {
            g_bar_count = 0u;
            __threadfence();
            atomicAdd(&g_bar_phase, 1u);
        } else {
            while (*php == ph) { __nanosleep(32); }
        }
        __threadfence();
    }
    __syncthreads();
}

// ---------------- dataflow sync ----------------
__device__ __forceinline__ void wait_ge(unsigned* c, unsigned tgt)
{
    if (threadIdx.x == 0) {
        volatile unsigned* vc = c;
        while (*vc < tgt) { __nanosleep(32); }
        __threadfence();
    }
    __syncthreads();
}
__device__ __forceinline__ void arrive(unsigned* c)
{
    if (threadIdx.x == 0) {
        __threadfence();
        atomicAdd(c, 1u);
    }
}

// ---------------- helpers ----------------
__device__ __forceinline__ float sigm(float x) { return 1.0f / (1.0f + __expf(-x)); }

__device__ __forceinline__ void mmaf16(float* d, const uint32_t* a, const uint32_t* b)
{
    asm volatile(
        "mma.sync.aligned.m16n8k16.row.col.f32.f16.f16.f32 "
        "{%0,%1,%2,%3}, {%4,%5,%6,%7}, {%8,%9}, {%0,%1,%2,%3};"
        : "+f"(d[0]), "+f"(d[1]), "+f"(d[2]), "+f"(d[3])
        : "r"(a[0]), "r"(a[1]), "r"(a[2]), "r"(a[3]), "r"(b[0]), "r"(b[1]));
}
__device__ __forceinline__ void ldsm4(uint32_t& r0, uint32_t& r1, uint32_t& r2,
                                      uint32_t& r3, uint32_t a)
{
    asm volatile("ldmatrix.sync.aligned.m8n8.x4.shared.b16 {%0,%1,%2,%3}, [%4];"
                 : "=r"(r0), "=r"(r1), "=r"(r2), "=r"(r3) : "r"(a));
}
__device__ __forceinline__ void ldsm2(uint32_t& r0, uint32_t& r1, uint32_t a)
{
    asm volatile("ldmatrix.sync.aligned.m8n8.x2.shared.b16 {%0,%1}, [%2];"
                 : "=r"(r0), "=r"(r1) : "r"(a));
}
__device__ __forceinline__ void cpasync16(uint32_t dst, const void* src)
{
    asm volatile("cp.async.cg.shared.global [%0], [%1], 16;" :: "r"(dst), "l"(src));
}
#define CP_COMMIT() asm volatile("cp.async.commit_group;" ::: "memory")
#define CP_WAIT0()  asm volatile("cp.async.wait_group 0;" ::: "memory")

// W loader: NROWS rows x 32 f16 each (4x16B segs/row)
template<int NROWS>
__device__ __forceinline__ void wload(uint32_t bb, const __half* w, int ldw, int c)
{
    constexpr int TOT = NROWS * 4;
#pragma unroll
    for (int i = 0; i < (TOT + NTH - 1) / NTH; i++) {
        int idx = threadIdx.x + i * NTH;
        if (TOT % NTH == 0 || idx < TOT) {
            int r = idx >> 2, q = idx & 3;
            cpasync16(bb + OFF_W + (uint32_t)(r * 80 + q * 16),
                      w + (size_t)r * ldw + (size_t)c * 32 + q * 8);
        }
    }
}

// ---------------- generic plain GEMM unit (prologue + logits) ----------------
struct MU {
    const __half *a, *w;
    const float *bias, *cadd;
    float* C;
    int lda, ldw, ldadd, ldc, nch, mrows, ncols;
};

__device__ __forceinline__ MU mk_mu(
    const __half* a, int lda, const __half* w, int ldw,
    const float* bias, const float* cadd, int ldadd,
    float* C, int ldc, int nch, int mrows, int ncols)
{
    MU u;
    u.a = a; u.w = w;
    u.bias = bias; u.cadd = cadd; u.C = C;
    u.lda = lda; u.ldw = ldw; u.ldadd = ldadd; u.ldc = ldc;
    u.nch = nch; u.mrows = mrows; u.ncols = ncols;
    return u;
}

template<int NF>
__device__ __noinline__ void mma_unit(const MU u, uint32_t smb)
{
    const int tid  = threadIdx.x;
    const int lane = tid & 31;
    const int w    = tid >> 5;
    const int wm   = w >> 2, wn = w & 3;
    const int gq   = lane >> 2, tq = lane & 3;
    constexpr int NP = NF / 2;
    constexpr int WROWS = NF * 32;

    float acc[2][NF][4];
#pragma unroll
    for (int i = 0; i < 2; i++)
#pragma unroll
        for (int j = 0; j < NF; j++)
#pragma unroll
            for (int k = 0; k < 4; k++) acc[i][j][k] = 0.0f;

    const int ar = tid >> 2, aq = tid & 3;
    const uint32_t soff = (uint32_t)(ar * 80 + aq * 16);

    const uint32_t a_off = (uint32_t)((wm * 32 + (lane & 15)) * 80 + (lane >> 4) * 16);
    uint32_t b_off[NP];
#pragma unroll
    for (int p = 0; p < NP; p++)
        b_off[p] = (uint32_t)((wn * (NF * 8) + p * 16 + ((lane >> 4) << 3) + (lane & 7)) * 80
                              + ((lane >> 3) & 1) * 16);

#define G_ASYNC(c, buf) do { \
    const uint32_t bb = smb + (uint32_t)(buf) * BUFSTRIDE; \
    size_t goA = (size_t)ar * u.lda + (size_t)(c) * 32 + aq * 8; \
    cpasync16(bb + OFF_AX + soff, u.a + goA); \
    wload<WROWS>(bb, u.w, u.ldw, (c)); \
    CP_COMMIT(); \
} while (0)

    G_ASYNC(0, 0);
    CP_WAIT0();
    __syncthreads();
    for (int c = 0; c < u.nch; c++) {
        if (c + 1 < u.nch) G_ASYNC(c + 1, (c + 1) & 1);
        const uint32_t bb = smb + (uint32_t)(c & 1) * BUFSTRIDE;
#pragma unroll
        for (int ks = 0; ks < 2; ks++) {
            const uint32_t ko = (uint32_t)(ks * 32);
            uint32_t bw[NF][2];
#pragma unroll
            for (int p = 0; p < NP; p++)
                ldsm4(bw[2*p][0], bw[2*p][1], bw[2*p+1][0], bw[2*p+1][1],
                      bb + OFF_W + b_off[p] + ko);
#pragma unroll
            for (int mf = 0; mf < 2; mf++) {
                uint32_t a4[4];
                ldsm4(a4[0], a4[1], a4[2], a4[3],
                      bb + OFF_AX + a_off + (uint32_t)(mf * 1280) + ko);
#pragma unroll
                for (int nf = 0; nf < NF; nf++) mmaf16(acc[mf][nf], a4, bw[nf]);
            }
        }
        if (c + 1 < u.nch) CP_WAIT0();
        __syncthreads();
    }
#undef G_ASYNC

#pragma unroll
    for (int mf = 0; mf < 2; mf++) {
#pragma unroll
        for (int half = 0; half < 2; half++) {
            int m = wm * 32 + mf * 16 + gq + half * 8;
            if (m >= u.mrows) continue;
            float* crow = u.C + (size_t)m * u.ldc;
            const float* car = u.cadd ? u.cadd + (size_t)m * u.ldadd : nullptr;
#pragma unroll
            for (int nf = 0; nf < NF; nf++) {
#pragma unroll
                for (int e = 0; e < 2; e++) {
                    int col = wn * (NF * 8) + nf * 8 + 2 * tq + e;
                    if (col < u.ncols) {
                        float v = acc[mf][nf][half * 2 + e];
                        if (u.bias) v += u.bias[col];
                        if (car) v += car[col];
                        crow[col] = v;
                    }
                }
            }
        }
    }
    __syncthreads();
}

// ---------------- fused layer-1/2 unit ----------------
struct FU {
    const __half *x, *h;
    const __half *w;                 // 192 rows x 1024
    const float* bc;
    float* hfp;
    __half* oa;
    int m0, j0;
};

__device__ __noinline__ void fused_l12(const FU u, uint32_t smb)
{
    const int tid  = threadIdx.x;
    const int lane = tid & 31;
    const int w    = tid >> 5;
    const int wm   = w >> 2, wn = w & 3;
    const int gq   = lane >> 2, tq = lane & 3;

    float acc[2][6][4];
#pragma unroll
    for (int i = 0; i < 2; i++)
#pragma unroll
        for (int j = 0; j < 6; j++)
#pragma unroll
            for (int k = 0; k < 4; k++) acc[i][j][k] = 0.0f;

    const int ar = tid >> 2, aq = tid & 3;
    const uint32_t soff = (uint32_t)(ar * 80 + aq * 16);

    const uint32_t a_off = (uint32_t)((wm * 32 + (lane & 15)) * 80 + (lane >> 4) * 16);
    uint32_t b_off[3];
#pragma unroll
    for (int p = 0; p < 3; p++)
        b_off[p] = (uint32_t)((wn * 48 + p * 16 + ((lane >> 4) << 3) + (lane & 7)) * 80
                              + ((lane >> 3) & 1) * 16);

#define F_ASYNC(c, buf) do { \
    const uint32_t bb = smb + (uint32_t)(buf) * BUFSTRIDE; \
    size_t goA = (size_t)(u.m0 + ar) * H + (size_t)(c) * 32 + aq * 8; \
    cpasync16(bb + OFF_AX + soff, u.x + goA); \
    cpasync16(bb + OFF_AH + soff, u.h + goA); \
    wload<192>(bb, u.w, H, (c)); \
    CP_COMMIT(); \
} while (0)

    F_ASYNC(0, 0);
    CP_WAIT0();
    __syncthreads();
    for (int c = 0; c < 32; c++) {
        if (c + 1 < 32) F_ASYNC(c + 1, (c + 1) & 1);
        const uint32_t bb = smb + (uint32_t)(c & 1) * BUFSTRIDE;
#pragma unroll
        for (int ks = 0; ks < 2; ks++) {
            const uint32_t ko = (uint32_t)(ks * 32);
            uint32_t bw[6][2];
#pragma unroll
            for (int p = 0; p < 3; p++)
                ldsm4(bw[2*p][0], bw[2*p][1], bw[2*p+1][0], bw[2*p+1][1],
                      bb + OFF_W + b_off[p] + ko);
#pragma unroll
            for (int mf = 0; mf < 2; mf++) {
                const uint32_t am = a_off + (uint32_t)(mf * 1280) + ko;
                uint32_t x4[4], h4[4];
                ldsm4(x4[0], x4[1], x4[2], x4[3], bb + OFF_AX + am);
                ldsm4(h4[0], h4[1], h4[2], h4[3], bb + OFF_AH + am);
#pragma unroll
                for (int nf = 0; nf < 3; nf++) mmaf16(acc[mf][nf], x4, bw[nf]);
#pragma unroll
                for (int nf = 3; nf < 6; nf++) mmaf16(acc[mf][nf], h4, bw[nf]);
            }
        }
        if (c + 1 < 32) CP_WAIT0();
        __syncthreads();
    }
#undef F_ASYNC

#pragma unroll
    for (int e = 0; e < 2; e++) {
        const int j = u.j0 + wn * 8 + 2 * tq + e;
        const float* bcb = u.bc + wn * 48 + 2 * tq + e;
        float b0 = bcb[0], b1 = bcb[8], b2 = bcb[16];
        float b3 = bcb[24], b4 = bcb[32], b5 = bcb[40];
#pragma unroll
        for (int mf = 0; mf < 2; mf++) {
#pragma unroll
            for (int half = 0; half < 2; half++) {
                int m = u.m0 + wm * 32 + mf * 16 + gq + half * 8;
                int ai = half * 2 + e;
                float ir = acc[mf][0][ai] + b0;
                float iz = acc[mf][1][ai] + b1;
                float in_ = acc[mf][2][ai] + b2;
                float hr = acc[mf][3][ai] + b3;
                float hz = acc[mf][4][ai] + b4;
                float hn = acc[mf][5][ai] + b5;
                float r = sigm(ir + hr), zz = sigm(iz + hz);
                float n = tanhf(in_ + r * hn);
                size_t idx = (size_t)m * H + j;
                float hv = (1.0f - zz) * n + zz * u.hfp[idx];
                u.hfp[idx] = hv;
                u.oa[idx] = __float2half_rn(hv);
            }
        }
    }
    __syncthreads();
}

// ---------------- fused layer-0 unit ----------------
struct F0 {
    const __half *h;
    const __half *w;                 // 192 rows x 1024
    const float* bc;
    const int* inp;
    int t, m0, j0;
    float* hfp;
    __half* oa;
};

__device__ __noinline__ void fused_l0(const F0 u, uint32_t smb)
{
    const int tid  = threadIdx.x;
    const int lane = tid & 31;
    const int w    = tid >> 5;
    const int wm   = w >> 3, wn = w & 7;
    const int gq   = lane >> 2, tq = lane & 3;

    float acc[2][3][4];
#pragma unroll
    for (int i = 0; i < 2; i++)
#pragma unroll
        for (int j = 0; j < 3; j++)
#pragma unroll
            for (int k = 0; k < 4; k++) acc[i][j][k] = 0.0f;

    const int ar = tid >> 2, aq = tid & 3;
    const uint32_t soff = (uint32_t)(ar * 80 + aq * 16);

    const uint32_t a_off = (uint32_t)((wm * 32 + (lane & 15)) * 80 + (lane >> 4) * 16);
    const uint32_t b_off0 = (uint32_t)((wn * 24 + ((lane >> 4) << 3) + (lane & 7)) * 80
                                       + ((lane >> 3) & 1) * 16);
    const uint32_t b_off2 = (uint32_t)((wn * 24 + 16 + (lane & 7)) * 80
                                       + ((lane >> 3) & 1) * 16);

#define Z_ASYNC(c, buf) do { \
    const uint32_t bb = smb + (uint32_t)(buf) * BUFSTRIDE; \
    if (tid < 256) { \
        size_t goA = (size_t)(u.m0 + ar) * H + (size_t)(c) * 32 + aq * 8; \
        cpasync16(bb + OFF_AX + soff, u.h + goA); } \
    wload<192>(bb, u.w, H, (c)); \
    CP_COMMIT(); \
} while (0)

    Z_ASYNC(0, 0);
    CP_WAIT0();
    __syncthreads();
    for (int c = 0; c < 32; c++) {
        if (c + 1 < 32) Z_ASYNC(c + 1, (c + 1) & 1);
        const uint32_t bb = smb + (uint32_t)(c & 1) * BUFSTRIDE;
#pragma unroll
        for (int ks = 0; ks < 2; ks++) {
            const uint32_t ko = (uint32_t)(ks * 32);
            uint32_t bw[3][2];
            ldsm4(bw[0][0], bw[0][1], bw[1][0], bw[1][1], bb + OFF_W + b_off0 + ko);
            ldsm2(bw[2][0], bw[2][1], bb + OFF_W + b_off2 + ko);
            uint32_t f4[2][4];
#pragma unroll
            for (int mf = 0; mf < 2; mf++) {
                const uint32_t am = a_off + (uint32_t)(mf * 1280) + ko;
                ldsm4(f4[mf][0], f4[mf][1], f4[mf][2], f4[mf][3], bb + OFF_AX + am);
            }
#pragma unroll
            for (int mf = 0; mf < 2; mf++)
#pragma unroll
                for (int nf = 0; nf < 3; nf++) mmaf16(acc[mf][nf], f4[mf], bw[nf]);
        }
        if (c + 1 < 32) CP_WAIT0();
        __syncthreads();
    }
#undef Z_ASYNC

#pragma unroll
    for (int e = 0; e < 2; e++) {
        const int j = u.j0 + wn * 8 + 2 * tq + e;
        const float* bcb = u.bc + wn * 24 + 2 * tq + e;
        float b0 = bcb[0], b1 = bcb[8], b2 = bcb[16];
#pragma unroll
        for (int mf = 0; mf < 2; mf++) {
#pragma unroll
            for (int half = 0; half < 2; half++) {
                int m = u.m0 + wm * 32 + mf * 16 + gq + half * 8;
                int ai = half * 2 + e;
                int tok = (u.t == 0) ? START_TOK : u.inp[m * S + u.t - 1];
                const float* tr = g_tokt + (size_t)tok * H3 + j;
                const float* gc = g_gi0c + (size_t)m * H3 + j;
                float ir = tr[0] + gc[0];
                float iz = tr[H] + gc[H];
                float in_ = tr[2 * H] + gc[2 * H];
                float hr = acc[mf][0][ai] + b0;
                float hz = acc[mf][1][ai] + b1;
                float hn = acc[mf][2][ai] + b2;
                float r = sigm(ir + hr), zz = sigm(iz + hz);
                float n = tanhf(in_ + r * hn);
                size_t idx = (size_t)m * H + j;
                float hv = (1.0f - zz) * n + zz * u.hfp[idx];
                u.hfp[idx] = hv;
                u.oa[idx] = __float2half_rn(hv);
            }
        }
    }
    __syncthreads();
}

// ---------------- persistent kernel ----------------
__global__ __launch_bounds__(NTH, 1) void decoder_k(
    const int* __restrict__ inputs, const float* __restrict__ z,
    const float* __restrict__ cond, const float* __restrict__ emb,
    const float* __restrict__ i2h_w, const float* __restrict__ i2h_b,
    const float* __restrict__ out_w, const float* __restrict__ out_b,
    const float* __restrict__ wih0, const float* __restrict__ whh0,
    const float* __restrict__ bih0, const float* __restrict__ bhh0,
    const float* __restrict__ wih1, const float* __restrict__ whh1,
    const float* __restrict__ bih1, const float* __restrict__ bhh1,
    const float* __restrict__ wih2, const float* __restrict__ whh2,
    const float* __restrict__ bih2, const float* __restrict__ bhh2,
    float* __restrict__ out)
{
    extern __shared__ __align__(16) char smem[];
    uint32_t smb;
    asm("{ .reg .u64 t; cvta.to.shared.u64 t, %1; cvt.u32.u64 %0, t; }"
        : "=r"(smb) : "l"(smem));

    const int tid = threadIdx.x;
    const unsigned nb = gridDim.x;
    const int gid = blockIdx.x * NTH + tid;
    const int gstride = nb * NTH;

    if (blockIdx.x == 0 && tid == 0) {
        for (int i = 0; i < 8; i++) g_cntA[i] = 0u;
        for (int i = 0; i < 4; i++) { g_cntC[i] = 0u; g_cntE[i] = 0u; g_cntL[i] = 0u; }
    }

    // ---- P0: weight conversions + gate-interleaved layouts ----
    for (int i = gid; i < 3072 * 1024; i += gstride) {
        int rd = i >> 10, k = i & 1023;
        int jb = rd / 192, r2 = rd - jb * 192;
        int jo = r2 / 24, r3 = r2 - jo * 24;
        int g = r3 >> 3, jr = r3 & 7;
        int j = jb * 64 + jo * 8 + jr;
        g_wc0[i] = __float2half_rn(whh0[(size_t)(g * H + j) * H + k]);
    }
    {
        const float* wi[2] = {wih1, wih2};
        const float* wr[2] = {whh1, whh2};
        __half* dw[2] = {g_wc1, g_wc2};
        for (int l = 0; l < 2; l++)
            for (int i = gid; i < 6144 * 1024; i += gstride) {
                int rd = i >> 10, k = i & 1023;
                int jb = rd / 192, r2 = rd - jb * 192;
                int jo = r2 / 48, r3 = r2 - jo * 48;
                int g = r3 >> 3, jr = r3 & 7;
                int j = jb * 32 + jo * 8 + jr;
                float v = (g < 3) ? wi[l][(size_t)(g * H + j) * H + k]
                                  : wr[l][(size_t)((g - 3) * H + j) * H + k];
                dw[l][i] = __float2half_rn(v);
            }
    }
    for (int i = gid; i < 3072; i += gstride) {
        int jb = i / 192, r2 = i - jb * 192;
        int jo = r2 / 24, r3 = r2 - jo * 24;
        int g = r3 >> 3, jr = r3 & 7;
        g_bc0[i] = bhh0[g * H + jb * 64 + jo * 8 + jr];
    }
    {
        const float* bi[2] = {bih1, bih2};
        const float* br[2] = {bhh1, bhh2};
        float* bd[2] = {g_bc1, g_bc2};
        for (int l = 0; l < 2; l++)
            for (int i = gid; i < 6144; i += gstride) {
                int jb = i / 192, r2 = i - jb * 192;
                int jo = r2 / 48, r3 = r2 - jo * 48;
                int g = r3 >> 3, jr = r3 & 7;
                int j = jb * 32 + jo * 8 + jr;
                bd[l][i] = (g < 3) ? bi[l][g * H + j] : br[l][(g - 3) * H + j];
            }
    }
    for (int i = gid; i < H * INSZ; i += gstride) g_i2h[i] = __float2half_rn(i2h_w[i]);
    for (int i = gid; i < H3 * EMB; i += gstride) {
        int r = i >> 9, c = i & 511;
        g_w0a[i] = __float2half_rn(wih0[(size_t)r * (EMB + INSZ) + c]);
    }
    for (int i = gid; i < H3 * H; i += gstride) {
        int r = i >> 10, c = i & 1023;
        g_w0b[i] = __float2half_rn(wih0[(size_t)r * (EMB + INSZ) + EMB + c]);
    }
    for (int i = gid; i < 128 * EMB; i += gstride) {
        int r = i >> 9, c = i & 511;
        g_emb[i] = __float2half_rn(r < V ? emb[r * EMB + c] : 0.0f);
    }
    for (int i = gid; i < 128 * H; i += gstride) {
        int r = i >> 10, c = i & 1023;
        g_ow[i]  = __float2half_rn(r < V ? out_w[(size_t)r * (H + INSZ) + c] : 0.0f);
        g_ow2[i] = __float2half_rn(r < V ? out_w[(size_t)r * (H + INSZ) + H + c] : 0.0f);
    }
    for (int i = gid; i < B * INSZ; i += gstride) {
        int b = i >> 10, jx = i & 1023;
        float v = (jx < 512) ? z[b * 512 + jx] : cond[b * 512 + jx - 512];
        g_dec[i] = __float2half_rn(v);
    }
    grid_bar();

    // ---- P2: prologue GEMMs (116 units) ----
    for (int u = blockIdx.x; u < 116; u += nb) {
        if (u < 32) {
            int mt = u & 3, nt = u >> 2;
            mma_unit<4>(mk_mu(
                g_dec + (size_t)(mt * 128) * INSZ, INSZ,
                g_i2h + (size_t)(nt * 128) * INSZ, INSZ,
                i2h_b + nt * 128, nullptr, 0,
                g_h0 + (size_t)(mt * 128) * H + nt * 128, H, 32, 128, 128), smb);
        } else if (u < 96) {
            int q = u - 32, mt = q & 3, nt = q >> 2;
            mma_unit<6>(mk_mu(
                g_dec + (size_t)(mt * 128) * INSZ, INSZ,
                g_w0b + (size_t)(nt * 192) * H, H,
                bih0 + nt * 192, nullptr, 0,
                g_gi0c + (size_t)(mt * 128) * H3 + nt * 192, H3, 32, 128, 192), smb);
        } else if (u < 112) {
            int nt = u - 96;
            mma_unit<6>(mk_mu(
                g_emb, EMB,
                g_w0a + (size_t)(nt * 192) * EMB, EMB,
                nullptr, nullptr, 0,
                g_tokt + nt * 192, H3, 16, V, 192), smb);
        } else {
            int mt = u - 112;
            mma_unit<4>(mk_mu(
                g_dec + (size_t)(mt * 128) * INSZ, INSZ,
                g_ow2, H,
                out_b, nullptr, 0,
                g_logc + (size_t)(mt * 128) * V, V, 32, 128, V), smb);
        }
    }
    grid_bar();

    // ---- P3: broadcast h_init into buffer 0 ----
    for (int i = gid; i < B * H; i += gstride) {
        float v = g_h0[i];
        g_h1[i] = v; g_h2[i] = v;
        __half hv = __float2half_rn(v);
        g_a0[0][i] = hv;
        g_a1[0][i] = hv;
        g_a2[0][i] = hv;
    }
    grid_bar();

    // ---- recurrent loop: barrier-free dataflow ----
    for (int t = 0; t < S; t++) {
        const int cur = t & 1, nxt = cur ^ 1;

        {
            const int U = 128 + (t > 0 ? 4 : 0);
            for (int u = blockIdx.x; u < U; u += nb) {
                if (u < 128) {
                    int mb = u & 7, jb = u >> 3;
                    if (t >= 1) wait_ge(&g_cntA[mb], 16u * (unsigned)t);
                    if (t >= 2) wait_ge(&g_cntC[mb >> 1], 32u * (unsigned)(t - 1));
                    F0 f;
                    f.h = g_a0[cur];
                    f.w = g_wc0 + (size_t)(jb * 192) * H;
                    f.bc = g_bc0 + jb * 192;
                    f.inp = inputs; f.t = t;
                    f.m0 = mb * 64; f.j0 = jb * 64;
                    f.hfp = g_h0; f.oa = g_a0[nxt];
                    fused_l0(f, smb);
                    arrive(&g_cntA[mb]);
                } else {
                    int mt = u - 128;
                    wait_ge(&g_cntE[mt], 32u * (unsigned)t);
                    mma_unit<4>(mk_mu(
                        g_a2[cur] + (size_t)(mt * 128) * H, H,
                        g_ow, H,
                        nullptr, g_logc + (size_t)(mt * 128) * V, V,
                        out + (size_t)(mt * 128) * (S * V) + (size_t)(t - 1) * V,
                        S * V, 32, 128, V), smb);
                    arrive(&g_cntL[mt]);
                }
            }
        }

        for (int u = blockIdx.x; u < 128; u += nb) {
            int mb = u & 3, jb = u >> 2;
            wait_ge(&g_cntA[2 * mb], 16u * (unsigned)(t + 1));
            wait_ge(&g_cntA[2 * mb + 1], 16u * (unsigned)(t + 1));
            if (t >= 1) wait_ge(&g_cntC[mb], 32u * (unsigned)t);
            if (t >= 2) wait_ge(&g_cntE[mb], 32u * (unsigned)(t - 1));
            FU f;
            f.x = g_a0[nxt]; f.h = g_a1[cur];
            f.w = g_wc1 + (size_t)(jb * 192) * H;
            f.bc = g_bc1 + jb * 192;
            f.m0 = mb * 128; f.j0 = jb * 32;
            f.hfp = g_h1; f.oa = g_a1[nxt];
            fused_l12(f, smb);
            arrive(&g_cntC[mb]);
        }

        for (int u = blockIdx.x; u < 128; u += nb) {
            int mb = u & 3, jb = u >> 2;
            wait_ge(&g_cntC[mb], 32u * (unsigned)(t + 1));
            if (t >= 1) wait_ge(&g_cntE[mb], 32u * (unsigned)t);
            if (t >= 2) wait_ge(&g_cntL[mb], (unsigned)(t - 1));
            FU f;
            f.x = g_a1[nxt]; f.h = g_a2[cur];
            f.w = g_wc2 + (size_t)(jb * 192) * H;
            f.bc = g_bc2 + jb * 192;
            f.m0 = mb * 128; f.j0 = jb * 32;
            f.hfp = g_h2; f.oa = g_a2[nxt];
            fused_l12(f, smb);
            arrive(&g_cntE[mb]);
        }
    }

    // ---- final logits ----
    for (int u = blockIdx.x; u < 4; u += nb) {
        int mt = u;
        wait_ge(&g_cntE[mt], 32u * (unsigned)S);
        mma_unit<4>(mk_mu(
            g_a2[S & 1] + (size_t)(mt * 128) * H, H,
            g_ow, H,
            nullptr, g_logc + (size_t)(mt * 128) * V, V,
            out + (size_t)(mt * 128) * (S * V) + (size_t)(S - 1) * V,
            S * V, 32, 128, V), smb);
    }
}

// ---------------- host ----------------
extern "C" void kernel_launch(void* const* d_in, const int* in_sizes, int n_in,
                              void* d_out, int out_size)
{
    (void)in_sizes; (void)n_in; (void)out_size;

    const int*   inputs = (const int*)  d_in[0];
    const float* z      = (const float*)d_in[1];
    const float* cond   = (const float*)d_in[2];
    const float* emb    = (const float*)d_in[4];
    const float* i2h_w  = (const float*)d_in[5];
    const float* i2h_b  = (const float*)d_in[6];
    const float* out_w  = (const float*)d_in[7];
    const float* out_b  = (const float*)d_in[8];
    const float* wih0 = (const float*)d_in[9];
    const float* whh0 = (const float*)d_in[10];
    const float* bih0 = (const float*)d_in[11];
    const float* bhh0 = (const float*)d_in[12];
    const float* wih1 = (const float*)d_in[13];
    const float* whh1 = (const float*)d_in[14];
    const float* bih1 = (const float*)d_in[15];
    const float* bhh1 = (const float*)d_in[16];
    const float* wih2 = (const float*)d_in[17];
    const float* whh2 = (const float*)d_in[18];
    const float* bih2 = (const float*)d_in[19];
    const float* bhh2 = (const float*)d_in[20];
    float* out = (float*)d_out;

    cudaFuncSetAttribute(decoder_k, cudaFuncAttributeMaxDynamicSharedMemorySize,
                         SMEM_TOTAL);

    int dev = 0;
    cudaGetDevice(&dev);
    int sms = 148;
    cudaDeviceGetAttribute(&sms, cudaDevAttrMultiProcessorCount, dev);
    int bpm = 1;
    cudaOccupancyMaxActiveBlocksPerMultiprocessor(&bpm, decoder_k, NTH, SMEM_TOTAL);
    if (bpm < 1) bpm = 1;

    decoder_k<<<sms * bpm, NTH, SMEM_TOTAL>>>(
        inputs, z, cond, emb, i2h_w, i2h_b, out_w, out_b,
        wih0, whh0, bih0, bhh0, wih1, whh1, bih1, bhh1,
        wih2, whh2, bih2, bhh2, out);
}